// round 2
// baseline (speedup 1.0000x reference)
#include <cuda_runtime.h>
#include <cuda_bf16.h>
#include <math.h>

// ---------------------------------------------------------------------------
// Problem constants
// ---------------------------------------------------------------------------
#define N_NODES   10000
#define N_EDGES   250000
#define FF        32
#define HIDDEN    64
#define NPATHS    11
#define FEAT      288
#define NRAD      352

#define EPB       64          // edges per block
#define BLK       256         // threads per block
#define HS_PITCH  66          // padded pitch for h[j][e]
#define M_PITCH   116         // padded pitch for M[e][elem] (115 used)

// PATHS = [(0,0,0),(0,1,1),(0,2,2),(1,0,1),(1,1,0),(1,1,2),
//          (1,2,1),(2,0,2),(2,1,1),(2,2,0),(2,2,2)]
__constant__ int c_PI[NPATHS]  = {0,0,0,1,1,1,1,2,2,2,2};
__constant__ int c_PJ[NPATHS]  = {0,1,2,0,1,1,2,0,1,2,2};
__constant__ int c_PK[NPATHS]  = {0,1,2,1,0,2,1,2,1,0,2};
// element-offset of path p in the per-edge M vector; sizes (2i+1)(2k+1):
// {1,3,5,9,3,15,9,25,15,5,25} -> total 115
__constant__ int c_OFF[NPATHS] = {0,1,4,9,18,21,36,45,70,85,90};
// PATH_W[p]/sqrt(25) = sqrt((2k+1)/cnt[k])/5 ; cnt = {k0:3, k1:4, k2:4}
__constant__ float c_PW[NPATHS] = {
    0.11547005383792515f, 0.17320508075688773f, 0.22360679774997896f,
    0.17320508075688773f, 0.11547005383792515f, 0.22360679774997896f,
    0.17320508075688773f, 0.22360679774997896f, 0.17320508075688773f,
    0.11547005383792515f, 0.22360679774997896f};

// Dense padded W3J: [path][a*25 + b*5 + c] (zeros outside (2i+1,2j+1,2k+1))
__device__ float g_w3j[NPATHS * 125];

// ---------------------------------------------------------------------------
// W3J setup: mirrors the reference exactly (SU(2) CG -> complex basis change
// -> pick real/imag by Frobenius norm -> normalize). fp64, ~5 us.
// ---------------------------------------------------------------------------
__device__ __forceinline__ double dfact(int n) {
    double r = 1.0;
    for (int i = 2; i <= n; ++i) r *= (double)i;
    return r;
}

__device__ double su2_cg(int j1, int j2, int j3, int m1, int m2, int m3) {
    if (m1 + m2 != m3) return 0.0;
    double pref = sqrt((2.0 * j3 + 1.0) * dfact(j1 + j2 - j3) * dfact(j1 - j2 + j3) *
                       dfact(-j1 + j2 + j3) / dfact(j1 + j2 + j3 + 1));
    pref *= sqrt(dfact(j3 + m3) * dfact(j3 - m3) * dfact(j1 - m1) * dfact(j1 + m1) *
                 dfact(j2 - m2) * dfact(j2 + m2));
    double s = 0.0;
    for (int k = 0; k <= j1 + j2 - j3; ++k) {
        int e1 = j1 + j2 - j3 - k, e2 = j1 - m1 - k, e3 = j2 + m2 - k;
        int e4 = j3 - j2 + m1 + k, e5 = j3 - j1 - m2 + k;
        if (e1 < 0 || e2 < 0 || e3 < 0 || e4 < 0 || e5 < 0) continue;
        double term = 1.0 / (dfact(k) * dfact(e1) * dfact(e2) * dfact(e3) *
                             dfact(e4) * dfact(e5));
        s += (k & 1) ? -term : term;
    }
    return pref * s;
}

// q(l)[r][c] including the (-1j)^l prefactor
__device__ __forceinline__ void qval(int l, int r, int c, double& re, double& im) {
    const double is2 = 0.70710678118654752440;
    int m = r - l;
    double a = 0.0, b = 0.0;
    if (m < 0) {
        if (c == l - m) a = is2;          // col l+|m|
        else if (c == l + m) b = -is2;    // col l-|m|
    } else if (m == 0) {
        if (c == l) a = 1.0;
    } else {
        double sg = (m & 1) ? -1.0 : 1.0;
        if (c == l + m) a = sg * is2;
        else if (c == l - m) b = sg * is2;
    }
    if (l == 1) { double ta = b, tb = -a; a = ta; b = tb; }   // *(-i)
    else if (l == 2) { a = -a; b = -b; }                      // *(-1)
    re = a; im = b;
}

__global__ void w3j_setup_kernel() {
    int p = blockIdx.x, t = threadIdx.x;
    int l1 = c_PI[p], l2 = c_PJ[p], l3 = c_PK[p];
    int d1 = 2 * l1 + 1, d2 = 2 * l2 + 1, d3 = 2 * l3 + 1;
    int n = d1 * d2 * d3;
    __shared__ double C[125], Wre[125], Wim[125];
    __shared__ double sel[2];

    for (int idx = t; idx < n; idx += blockDim.x) {
        int i = idx / (d2 * d3), k = (idx / d3) % d2, m = idx % d3;
        C[idx] = su2_cg(l1, l2, l3, i - l1, k - l2, m - l3);
    }
    __syncthreads();

    for (int idx = t; idx < n; idx += blockDim.x) {
        int jj = idx / (d2 * d3), ll = (idx / d3) % d2, nn = idx % d3;
        double sre = 0.0, sim = 0.0;
        for (int i = 0; i < d1; ++i)
            for (int k = 0; k < d2; ++k)
                for (int m = 0; m < d3; ++m) {
                    double cc = C[(i * d2 + k) * d3 + m];
                    if (cc == 0.0) continue;
                    double a1, b1, a2, b2, a3, b3;
                    qval(l1, i, jj, a1, b1);
                    qval(l2, k, ll, a2, b2);
                    qval(l3, m, nn, a3, b3);
                    double pr = a1 * a2 - b1 * b2;
                    double pi = a1 * b2 + b1 * a2;
                    double rr = pr * a3 + pi * b3;   // * conj(q3)
                    double ri = pi * a3 - pr * b3;
                    sre += cc * rr;
                    sim += cc * ri;
                }
        Wre[idx] = sre; Wim[idx] = sim;
    }
    __syncthreads();

    if (t == 0) {
        double nr = 0.0, ni = 0.0;
        for (int idx = 0; idx < n; ++idx) {
            nr += Wre[idx] * Wre[idx];
            ni += Wim[idx] * Wim[idx];
        }
        nr = sqrt(nr); ni = sqrt(ni);
        sel[0] = (nr >= ni) ? 1.0 : 0.0;
        sel[1] = (nr >= ni) ? nr : ni;
    }
    __syncthreads();

    bool useRe = sel[0] > 0.5;
    double inv = 1.0 / sel[1];
    for (int idx = t; idx < 125; idx += blockDim.x) {
        int a = idx / 25, b = (idx / 5) % 5, c = idx % 5;
        float v = 0.0f;
        if (a < d1 && b < d2 && c < d3) {
            double wv = useRe ? Wre[(a * d2 + b) * d3 + c] : Wim[(a * d2 + b) * d3 + c];
            v = (float)(wv * inv);
        }
        g_w3j[p * 125 + idx] = v;
    }
}

// ---------------------------------------------------------------------------
__global__ void zero_kernel(float* __restrict__ out, int n) {
    int i = blockIdx.x * blockDim.x + threadIdx.x;
    if (i < n) out[i] = 0.0f;
}

// ---------------------------------------------------------------------------
// packed f32x2 helpers
// ---------------------------------------------------------------------------
__device__ __forceinline__ unsigned long long dupf(float w) {
    unsigned long long r;
    unsigned u = __float_as_uint(w);
    asm("mov.b64 %0, {%1, %1};" : "=l"(r) : "r"(u));
    return r;
}
__device__ __forceinline__ void fma2(unsigned long long& d, unsigned long long a,
                                     unsigned long long b) {
    asm("fma.rn.f32x2 %0, %1, %2, %0;" : "+l"(d) : "l"(a), "l"(b));
}

// dynamic smem layout (float slots)
#define SM_W2S   0                       // 16*352 = 5632
#define SM_HS    (SM_W2S + 5632)         // HS_PITCH*64 = 4224
#define SM_MSM   (SM_HS + 4224)          // M_PITCH*64 = 7424
#define SM_YSM   (SM_MSM + 7424)         // 8*64 = 512
#define SM_BES   (SM_YSM + 512)          // 8*64 = 512
#define SM_CUT   (SM_BES + 512)          // 64
#define SM_SRC   (SM_CUT + 64)           // 64 (int)
#define SM_DST   (SM_SRC + 64)           // 64 (int)
#define SM_TOTALF (SM_DST + 64)          // 18496 floats
#define SMEM_BYTES (SM_TOTALF * 4)       // 73984 B

__global__ void __launch_bounds__(BLK) conv_kernel(
    const float* __restrict__ nodes, const float* __restrict__ pos,
    const int* __restrict__ src, const int* __restrict__ dst,
    const float* __restrict__ w1, const float* __restrict__ b1,
    const float* __restrict__ w2, const float* __restrict__ b2,
    float* __restrict__ out)
{
    extern __shared__ float smf[];
    float* w2s   = smf + SM_W2S;
    float* hs    = smf + SM_HS;
    float* Msm   = smf + SM_MSM;
    float* ysm   = smf + SM_YSM;
    float* bessm = smf + SM_BES;
    float* cutsm = smf + SM_CUT;
    int*   srcsm = (int*)(smf + SM_SRC);
    int*   dstsm = (int*)(smf + SM_DST);

    const int t  = threadIdx.x;
    const int u  = t & 31;       // lane == channel
    const int wr = t >> 5;       // warp 0..7 owns edges 8*wr .. 8*wr+7

    // ================= Phase A: per-edge geometry (threads 0..63) ==========
    if (t < EPB) {
        int eg = blockIdx.x * EPB + t;
        float cut = 0.f, ux = 0.f, uy = 0.f, uz = 0.f;
        int sn = 0, dn = 0;
        float besv[8];
        #pragma unroll
        for (int n = 0; n < 8; ++n) besv[n] = 0.f;
        if (eg < N_EDGES) {
            sn = src[eg]; dn = dst[eg];
            float px = pos[3 * sn]     - pos[3 * dn];
            float py = pos[3 * sn + 1] - pos[3 * dn + 1];
            float pz = pos[3 * sn + 2] - pos[3 * dn + 2];
            float d  = sqrtf(px * px + py * py + pz * pz);
            float rin = 1.0f / fmaxf(d, 1e-12f);
            ux = px * rin; uy = py * rin; uz = pz * rin;
            if (d < 4.0f) {
                float uu = d * 0.25f;
                float u2 = uu * uu, u4 = u2 * u2, u5 = u4 * uu;
                cut = 1.0f - 6.0f * u5 + 5.0f * u5 * uu;
            }
            float tt = d * 0.2f;                       // d / BESSEL_END
            if (tt > 0.0f && tt < 1.0f) {
                float cc = 0.6324555320336759f / tt;   // sqrt(2/5)/t
                #pragma unroll
                for (int n = 1; n <= 8; ++n)
                    besv[n - 1] = cc * sinf((float)n * 3.14159265358979323846f * tt);
            }
        }
        cutsm[t] = cut;
        srcsm[t] = sn; dstsm[t] = dn;
        #pragma unroll
        for (int n = 0; n < 8; ++n) bessm[t * 8 + n] = besv[n];
        // spherical harmonics: y1 = sqrt3*[y,z,x]; y2 = [s15 xy, s15 yz,
        //   s5/2(3z^2-1), s15 xz, s15/2 (x^2-y^2)]
        const float s3 = 1.7320508075688772f, s15 = 3.872983346207417f;
        const float s5h = 1.118033988749895f, s15h = 1.9364916731037085f;
        ysm[t * 8 + 0] = s3 * uy;
        ysm[t * 8 + 1] = s3 * uz;
        ysm[t * 8 + 2] = s3 * ux;
        ysm[t * 8 + 3] = s15 * ux * uy;
        ysm[t * 8 + 4] = s15 * uy * uz;
        ysm[t * 8 + 5] = s5h * (3.0f * uz * uz - 1.0f);
        ysm[t * 8 + 6] = s15 * ux * uz;
        ysm[t * 8 + 7] = s15h * (ux * ux - uy * uy);
    }
    __syncthreads();

    // ================= Phase B: hidden layer h = silu(bes@w1+b1) ===========
    {
        int j   = t & 63;
        int eg0 = (t >> 6) * 16;
        float w1r[8];
        #pragma unroll
        for (int n = 0; n < 8; ++n) w1r[n] = w1[n * HIDDEN + j];
        float b1r = b1[j];
        #pragma unroll 4
        for (int ee = 0; ee < 16; ++ee) {
            int e = eg0 + ee;
            float a = b1r;
            #pragma unroll
            for (int n = 0; n < 8; ++n) a = fmaf(bessm[e * 8 + n], w1r[n], a);
            hs[j * HS_PITCH + e] = a / (1.0f + expf(-a));   // silu
        }
    }
    // (sync folded into first GEMM stage sync)

    // ================= Phase C: GEMM h[64x64] @ w2[64x352] =================
    unsigned long long acc[NPATHS][4];
    #pragma unroll
    for (int p = 0; p < NPATHS; ++p)
        #pragma unroll
        for (int q = 0; q < 4; ++q) acc[p][q] = 0ull;

    for (int s = 0; s < 4; ++s) {
        __syncthreads();
        {   // copy 16 rows of w2 (5632 floats = 2816 u64 = 256*11)
            const unsigned long long* gsrc =
                reinterpret_cast<const unsigned long long*>(w2 + s * 5632);
            unsigned long long* sdst = reinterpret_cast<unsigned long long*>(w2s);
            #pragma unroll
            for (int r = 0; r < 11; ++r) sdst[r * BLK + t] = gsrc[r * BLK + t];
        }
        __syncthreads();
        #pragma unroll 2
        for (int jl = 0; jl < 16; ++jl) {
            int jg = s * 16 + jl;
            const unsigned long long* hp =
                reinterpret_cast<const unsigned long long*>(&hs[jg * HS_PITCH + 8 * wr]);
            unsigned long long h0 = hp[0], h1 = hp[1], h2 = hp[2], h3 = hp[3];
            #pragma unroll
            for (int p = 0; p < NPATHS; ++p) {
                unsigned long long wv = dupf(w2s[jl * NRAD + p * 32 + u]);
                fma2(acc[p][0], wv, h0);
                fma2(acc[p][1], wv, h1);
                fma2(acc[p][2], wv, h2);
                fma2(acc[p][3], wv, h3);
            }
        }
    }

    // ================= Phase D: per-edge M matrices (own warp's edges) =====
    int   md_w3j[4], md_nb[4], md_yoff[4];
    float md_pw[4];
    bool  md_v[4];
    #pragma unroll
    for (int g = 0; g < 4; ++g) {
        int idx = g * 32 + u;
        md_v[g] = (idx < 115);
        int p = 10;
        if (md_v[g]) { while (c_OFF[p] > idx) --p; } else { p = 0; }
        int r  = idx - c_OFF[p];
        int wk = 2 * c_PK[p] + 1;
        int a  = r / wk;
        int c  = r - a * wk;
        int jj = c_PJ[p];
        md_w3j[g]  = p * 125 + a * 25 + c;
        md_nb[g]   = 2 * jj + 1;
        md_yoff[g] = (jj == 0) ? -1 : ((jj == 1) ? 0 : 3);
        md_pw[g]   = c_PW[p];
    }
    for (int q = 0; q < 8; ++q) {
        int e = 8 * wr + q;
        #pragma unroll
        for (int g = 0; g < 4; ++g) {
            if (!md_v[g]) continue;
            const float* wb = g_w3j + md_w3j[g];
            float a;
            if (md_yoff[g] < 0) {
                a = wb[0];
            } else {
                a = 0.f;
                for (int b = 0; b < md_nb[g]; ++b)
                    a = fmaf(wb[5 * b], ysm[e * 8 + md_yoff[g] + b], a);
            }
            Msm[e * M_PITCH + g * 32 + u] = a * md_pw[g];
        }
    }
    __syncwarp();

    // ================= Phase E: tensor product + scatter ===================
    float b2r[NPATHS];
    #pragma unroll
    for (int p = 0; p < NPATHS; ++p) b2r[p] = b2[p * 32 + u];

    #pragma unroll
    for (int q = 0; q < 8; ++q) {
        int e = 8 * wr + q;
        float cutv = cutsm[e];
        int sn = srcsm[e], dn = dstsm[e];
        const float* xb = nodes + (size_t)sn * FEAT;
        float x0r = xb[u];
        float x1r[3], x2r[5];
        #pragma unroll
        for (int a = 0; a < 3; ++a) x1r[a] = xb[32 + u * 3 + a];
        #pragma unroll
        for (int a = 0; a < 5; ++a) x2r[a] = xb[128 + u * 5 + a];

        float wv[NPATHS];
        #pragma unroll
        for (int p = 0; p < NPATHS; ++p) {
            unsigned long long v = acc[p][q >> 1];
            unsigned bits = (q & 1) ? (unsigned)(v >> 32) : (unsigned)v;
            wv[p] = (__uint_as_float(bits) + b2r[p]) * cutv;
        }

        const float* Mb = Msm + e * M_PITCH;
        float m0 = 0.f, m1[3] = {0.f, 0.f, 0.f}, m2[5] = {0.f, 0.f, 0.f, 0.f, 0.f};
        float s;
        // p0 (0,0,0)
        m0 = fmaf(wv[0], x0r * Mb[0], m0);
        // p1 (0,1,1)
        #pragma unroll
        for (int c = 0; c < 3; ++c) m1[c] = fmaf(wv[1], x0r * Mb[1 + c], m1[c]);
        // p2 (0,2,2)
        #pragma unroll
        for (int c = 0; c < 5; ++c) m2[c] = fmaf(wv[2], x0r * Mb[4 + c], m2[c]);
        // p3 (1,0,1)
        #pragma unroll
        for (int c = 0; c < 3; ++c) {
            s = x1r[0] * Mb[9 + c] + x1r[1] * Mb[12 + c] + x1r[2] * Mb[15 + c];
            m1[c] = fmaf(wv[3], s, m1[c]);
        }
        // p4 (1,1,0)
        s = x1r[0] * Mb[18] + x1r[1] * Mb[19] + x1r[2] * Mb[20];
        m0 = fmaf(wv[4], s, m0);
        // p5 (1,1,2)
        #pragma unroll
        for (int c = 0; c < 5; ++c) {
            s = x1r[0] * Mb[21 + c] + x1r[1] * Mb[26 + c] + x1r[2] * Mb[31 + c];
            m2[c] = fmaf(wv[5], s, m2[c]);
        }
        // p6 (1,2,1)
        #pragma unroll
        for (int c = 0; c < 3; ++c) {
            s = x1r[0] * Mb[36 + c] + x1r[1] * Mb[39 + c] + x1r[2] * Mb[42 + c];
            m1[c] = fmaf(wv[6], s, m1[c]);
        }
        // p7 (2,0,2)
        #pragma unroll
        for (int c = 0; c < 5; ++c) {
            s = 0.f;
            #pragma unroll
            for (int a = 0; a < 5; ++a) s = fmaf(x2r[a], Mb[45 + a * 5 + c], s);
            m2[c] = fmaf(wv[7], s, m2[c]);
        }
        // p8 (2,1,1)
        #pragma unroll
        for (int c = 0; c < 3; ++c) {
            s = 0.f;
            #pragma unroll
            for (int a = 0; a < 5; ++a) s = fmaf(x2r[a], Mb[70 + a * 3 + c], s);
            m1[c] = fmaf(wv[8], s, m1[c]);
        }
        // p9 (2,2,0)
        s = 0.f;
        #pragma unroll
        for (int a = 0; a < 5; ++a) s = fmaf(x2r[a], Mb[85 + a], s);
        m0 = fmaf(wv[9], s, m0);
        // p10 (2,2,2)
        #pragma unroll
        for (int c = 0; c < 5; ++c) {
            s = 0.f;
            #pragma unroll
            for (int a = 0; a < 5; ++a) s = fmaf(x2r[a], Mb[90 + a * 5 + c], s);
            m2[c] = fmaf(wv[10], s, m2[c]);
        }

        float* ob = out + (size_t)dn * FEAT;
        atomicAdd(&ob[u], m0);
        #pragma unroll
        for (int a = 0; a < 3; ++a) atomicAdd(&ob[32 + u * 3 + a], m1[a]);
        #pragma unroll
        for (int a = 0; a < 5; ++a) atomicAdd(&ob[128 + u * 5 + a], m2[a]);
    }
}

// ---------------------------------------------------------------------------
extern "C" void kernel_launch(void* const* d_in, const int* in_sizes, int n_in,
                              void* d_out, int out_size) {
    const float* nodes = (const float*)d_in[0];
    const float* pos   = (const float*)d_in[1];
    const int*   src   = (const int*)d_in[2];
    const int*   dst   = (const int*)d_in[3];
    const float* w1    = (const float*)d_in[4];
    const float* b1    = (const float*)d_in[5];
    const float* w2    = (const float*)d_in[6];
    const float* b2    = (const float*)d_in[7];
    float* out = (float*)d_out;

    w3j_setup_kernel<<<NPATHS, 128>>>();
    zero_kernel<<<(out_size + 255) / 256, 256>>>(out, out_size);

    cudaFuncSetAttribute(conv_kernel,
                         cudaFuncAttributeMaxDynamicSharedMemorySize, SMEM_BYTES);
    int nblocks = (N_EDGES + EPB - 1) / EPB;
    conv_kernel<<<nblocks, BLK, SMEM_BYTES>>>(nodes, pos, src, dst,
                                              w1, b1, w2, b2, out);
}

// round 3
// speedup vs baseline: 1.1475x; 1.1475x over previous
#include <cuda_runtime.h>
#include <cuda_bf16.h>
#include <math.h>

// ---------------------------------------------------------------------------
// Problem constants
// ---------------------------------------------------------------------------
#define N_NODES   10000
#define N_EDGES   250000
#define FF        32
#define HIDDEN    64
#define NPATHS    11
#define FEAT      288
#define NRAD      352

#define EPB       64          // edges per block
#define BLK       256         // threads per block
#define HS_PITCH  66          // padded pitch for h[j][e]
#define M_PITCH   116         // padded pitch for M[e][elem] (115 used)

// PATHS = [(0,0,0),(0,1,1),(0,2,2),(1,0,1),(1,1,0),(1,1,2),
//          (1,2,1),(2,0,2),(2,1,1),(2,2,0),(2,2,2)]
__constant__ int c_PI[NPATHS]  = {0,0,0,1,1,1,1,2,2,2,2};
__constant__ int c_PJ[NPATHS]  = {0,1,2,0,1,1,2,0,1,2,2};
__constant__ int c_PK[NPATHS]  = {0,1,2,1,0,2,1,2,1,0,2};
// element-offset of path p in the per-edge M vector; sizes (2i+1)(2k+1):
// {1,3,5,9,3,15,9,25,15,5,25} -> total 115
__constant__ int c_OFF[NPATHS] = {0,1,4,9,18,21,36,45,70,85,90};
// PATH_W[p]/sqrt(25) = sqrt((2k+1)/cnt[k])/5 ; cnt = {k0:3, k1:4, k2:4}
__constant__ float c_PW[NPATHS] = {
    0.11547005383792515f, 0.17320508075688773f, 0.22360679774997896f,
    0.17320508075688773f, 0.11547005383792515f, 0.22360679774997896f,
    0.17320508075688773f, 0.22360679774997896f, 0.17320508075688773f,
    0.11547005383792515f, 0.22360679774997896f};

// Dense padded W3J: [path][a*25 + b*5 + c] (zeros outside (2i+1,2j+1,2k+1))
__device__ float g_w3j[NPATHS * 125];

// ---------------------------------------------------------------------------
// Setup kernel: zero the output AND compute W3J (fp32 mirror of the
// reference: SU(2) CG -> complex basis change -> pick re/im by norm ->
// normalize). fp32 is fine: values are O(0.1-1), roundoff ~1e-6 relative,
// test tolerance is 1e-3.
// ---------------------------------------------------------------------------
__device__ __forceinline__ float ffact(int n) {
    float r = 1.0f;
    for (int i = 2; i <= n; ++i) r *= (float)i;
    return r;
}

__device__ float su2_cg_f(int j1, int j2, int j3, int m1, int m2, int m3) {
    if (m1 + m2 != m3) return 0.0f;
    float pref = sqrtf((2.0f * j3 + 1.0f) * ffact(j1 + j2 - j3) * ffact(j1 - j2 + j3) *
                       ffact(-j1 + j2 + j3) / ffact(j1 + j2 + j3 + 1));
    pref *= sqrtf(ffact(j3 + m3) * ffact(j3 - m3) * ffact(j1 - m1) * ffact(j1 + m1) *
                  ffact(j2 - m2) * ffact(j2 + m2));
    float s = 0.0f;
    for (int k = 0; k <= j1 + j2 - j3; ++k) {
        int e1 = j1 + j2 - j3 - k, e2 = j1 - m1 - k, e3 = j2 + m2 - k;
        int e4 = j3 - j2 + m1 + k, e5 = j3 - j1 - m2 + k;
        if (e1 < 0 || e2 < 0 || e3 < 0 || e4 < 0 || e5 < 0) continue;
        float term = 1.0f / (ffact(k) * ffact(e1) * ffact(e2) * ffact(e3) *
                             ffact(e4) * ffact(e5));
        s += (k & 1) ? -term : term;
    }
    return pref * s;
}

// q(l)[r][c] including the (-1j)^l prefactor
__device__ __forceinline__ void qval_f(int l, int r, int c, float& re, float& im) {
    const float is2 = 0.70710678118654752440f;
    int m = r - l;
    float a = 0.0f, b = 0.0f;
    if (m < 0) {
        if (c == l - m) a = is2;          // col l+|m|
        else if (c == l + m) b = -is2;    // col l-|m|
    } else if (m == 0) {
        if (c == l) a = 1.0f;
    } else {
        float sg = (m & 1) ? -1.0f : 1.0f;
        if (c == l + m) a = sg * is2;
        else if (c == l - m) b = sg * is2;
    }
    if (l == 1) { float ta = b, tb = -a; a = ta; b = tb; }   // *(-i)
    else if (l == 2) { a = -a; b = -b; }                      // *(-1)
    re = a; im = b;
}

#define SETUP_BLOCKS 512

__global__ void __launch_bounds__(128) setup_kernel(float* __restrict__ out, int n4) {
    // grid-stride zero of the output (float4)
    {
        float4* o4 = (float4*)out;
        float4 z = make_float4(0.f, 0.f, 0.f, 0.f);
        for (int i = blockIdx.x * blockDim.x + threadIdx.x; i < n4;
             i += gridDim.x * blockDim.x)
            o4[i] = z;
    }
    if (blockIdx.x >= NPATHS) return;

    int p = blockIdx.x, t = threadIdx.x;
    int l1 = c_PI[p], l2 = c_PJ[p], l3 = c_PK[p];
    int d1 = 2 * l1 + 1, d2 = 2 * l2 + 1, d3 = 2 * l3 + 1;
    int n = d1 * d2 * d3;
    __shared__ float C[125], Wre[125], Wim[125];
    __shared__ float sel[2];

    for (int idx = t; idx < n; idx += blockDim.x) {
        int i = idx / (d2 * d3), k = (idx / d3) % d2, m = idx % d3;
        C[idx] = su2_cg_f(l1, l2, l3, i - l1, k - l2, m - l3);
    }
    __syncthreads();

    for (int idx = t; idx < n; idx += blockDim.x) {
        int jj = idx / (d2 * d3), ll = (idx / d3) % d2, nn = idx % d3;
        float sre = 0.0f, sim = 0.0f;
        for (int i = 0; i < d1; ++i)
            for (int k = 0; k < d2; ++k)
                for (int m = 0; m < d3; ++m) {
                    float cc = C[(i * d2 + k) * d3 + m];
                    if (cc == 0.0f) continue;
                    float a1, b1, a2, b2, a3, b3;
                    qval_f(l1, i, jj, a1, b1);
                    qval_f(l2, k, ll, a2, b2);
                    qval_f(l3, m, nn, a3, b3);
                    float pr = a1 * a2 - b1 * b2;
                    float pi = a1 * b2 + b1 * a2;
                    float rr = pr * a3 + pi * b3;   // * conj(q3)
                    float ri = pi * a3 - pr * b3;
                    sre += cc * rr;
                    sim += cc * ri;
                }
        Wre[idx] = sre; Wim[idx] = sim;
    }
    __syncthreads();

    if (t == 0) {
        float nr = 0.0f, ni = 0.0f;
        for (int idx = 0; idx < n; ++idx) {
            nr += Wre[idx] * Wre[idx];
            ni += Wim[idx] * Wim[idx];
        }
        nr = sqrtf(nr); ni = sqrtf(ni);
        sel[0] = (nr >= ni) ? 1.0f : 0.0f;
        sel[1] = (nr >= ni) ? nr : ni;
    }
    __syncthreads();

    bool useRe = sel[0] > 0.5f;
    float inv = 1.0f / sel[1];
    for (int idx = t; idx < 125; idx += blockDim.x) {
        int a = idx / 25, b = (idx / 5) % 5, c = idx % 5;
        float v = 0.0f;
        if (a < d1 && b < d2 && c < d3) {
            float wv = useRe ? Wre[(a * d2 + b) * d3 + c] : Wim[(a * d2 + b) * d3 + c];
            v = wv * inv;
        }
        g_w3j[p * 125 + idx] = v;
    }
}

// ---------------------------------------------------------------------------
// packed f32x2 helpers
// ---------------------------------------------------------------------------
__device__ __forceinline__ unsigned long long dupf(float w) {
    unsigned long long r;
    unsigned u = __float_as_uint(w);
    asm("mov.b64 %0, {%1, %1};" : "=l"(r) : "r"(u));
    return r;
}
__device__ __forceinline__ void fma2(unsigned long long& d, unsigned long long a,
                                     unsigned long long b) {
    asm("fma.rn.f32x2 %0, %1, %2, %0;" : "+l"(d) : "l"(a), "l"(b));
}

// dynamic smem layout (float slots)
#define SM_W2S   0                        // 16*352 = 5632
#define SM_HS    (SM_W2S + 5632)          // HS_PITCH*64 = 4224
#define SM_MSM   (SM_HS + 4224)           // M_PITCH*64 = 7424
#define SM_YSM   (SM_MSM + 7424)          // 8*64 = 512
#define SM_BES   (SM_YSM + 512)           // 8*64 = 512
#define SM_CUT   (SM_BES + 512)           // 64
#define SM_SRC   (SM_CUT + 64)            // 64 (int)
#define SM_DST   (SM_SRC + 64)            // 64 (int)
#define SM_W3J   (SM_DST + 64)            // 1375
#define SM_TOTALF (SM_W3J + 1375)         // 19871 floats
#define SMEM_BYTES (SM_TOTALF * 4)        // 79484 B

__global__ void __launch_bounds__(BLK) conv_kernel(
    const float* __restrict__ nodes, const float* __restrict__ pos,
    const int* __restrict__ src, const int* __restrict__ dst,
    const float* __restrict__ w1, const float* __restrict__ b1,
    const float* __restrict__ w2, const float* __restrict__ b2,
    float* __restrict__ out)
{
    extern __shared__ float smf[];
    float* w2s   = smf + SM_W2S;
    float* hs    = smf + SM_HS;
    float* Msm   = smf + SM_MSM;
    float* ysm   = smf + SM_YSM;
    float* bessm = smf + SM_BES;
    float* cutsm = smf + SM_CUT;
    int*   srcsm = (int*)(smf + SM_SRC);
    int*   dstsm = (int*)(smf + SM_DST);
    float* w3jsm = smf + SM_W3J;

    const int t  = threadIdx.x;
    const int u  = t & 31;       // lane == channel
    const int wr = t >> 5;       // warp 0..7 owns edges 8*wr .. 8*wr+7

    // stage W3J table into smem (1375 floats)
    #pragma unroll
    for (int r = 0; r < 6; ++r) {
        int idx = r * BLK + t;
        if (idx < NPATHS * 125) w3jsm[idx] = g_w3j[idx];
    }

    // ================= Phase A: per-edge geometry (threads 0..63) ==========
    if (t < EPB) {
        int eg = blockIdx.x * EPB + t;
        float cut = 0.f, ux = 0.f, uy = 0.f, uz = 0.f;
        int sn = 0, dn = 0;
        float besv[8];
        #pragma unroll
        for (int n = 0; n < 8; ++n) besv[n] = 0.f;
        if (eg < N_EDGES) {
            sn = src[eg]; dn = dst[eg];
            float px = pos[3 * sn]     - pos[3 * dn];
            float py = pos[3 * sn + 1] - pos[3 * dn + 1];
            float pz = pos[3 * sn + 2] - pos[3 * dn + 2];
            float d  = sqrtf(px * px + py * py + pz * pz);
            float rin = 1.0f / fmaxf(d, 1e-12f);
            ux = px * rin; uy = py * rin; uz = pz * rin;
            if (d < 4.0f) {
                float uu = d * 0.25f;
                float u2 = uu * uu, u4 = u2 * u2, u5 = u4 * uu;
                cut = 1.0f - 6.0f * u5 + 5.0f * u5 * uu;
            }
            float tt = d * 0.2f;                       // d / BESSEL_END
            if (tt > 0.0f && tt < 1.0f) {
                float cc = 0.6324555320336759f / tt;   // sqrt(2/5)/t
                #pragma unroll
                for (int n = 1; n <= 8; ++n)
                    besv[n - 1] = cc * sinf((float)n * 3.14159265358979323846f * tt);
            }
        }
        cutsm[t] = cut;
        srcsm[t] = sn; dstsm[t] = dn;
        #pragma unroll
        for (int n = 0; n < 8; ++n) bessm[t * 8 + n] = besv[n];
        // spherical harmonics: y1 = sqrt3*[y,z,x]; y2 = [s15 xy, s15 yz,
        //   s5/2(3z^2-1), s15 xz, s15/2 (x^2-y^2)]
        const float s3 = 1.7320508075688772f, s15 = 3.872983346207417f;
        const float s5h = 1.118033988749895f, s15h = 1.9364916731037085f;
        ysm[t * 8 + 0] = s3 * uy;
        ysm[t * 8 + 1] = s3 * uz;
        ysm[t * 8 + 2] = s3 * ux;
        ysm[t * 8 + 3] = s15 * ux * uy;
        ysm[t * 8 + 4] = s15 * uy * uz;
        ysm[t * 8 + 5] = s5h * (3.0f * uz * uz - 1.0f);
        ysm[t * 8 + 6] = s15 * ux * uz;
        ysm[t * 8 + 7] = s15h * (ux * ux - uy * uy);
    }
    __syncthreads();

    // ================= Phase B: hidden layer h = silu(bes@w1+b1) ===========
    {
        int j   = t & 63;
        int eg0 = (t >> 6) * 16;
        float w1r[8];
        #pragma unroll
        for (int n = 0; n < 8; ++n) w1r[n] = w1[n * HIDDEN + j];
        float b1r = b1[j];
        #pragma unroll 4
        for (int ee = 0; ee < 16; ++ee) {
            int e = eg0 + ee;
            float a = b1r;
            #pragma unroll
            for (int n = 0; n < 8; ++n) a = fmaf(bessm[e * 8 + n], w1r[n], a);
            hs[j * HS_PITCH + e] = a / (1.0f + __expf(-a));   // silu
        }
    }
    // (sync folded into first GEMM stage sync)

    // ================= Phase C: GEMM h[64x64] @ w2[64x352] =================
    unsigned long long acc[NPATHS][4];
    #pragma unroll
    for (int p = 0; p < NPATHS; ++p)
        #pragma unroll
        for (int q = 0; q < 4; ++q) acc[p][q] = 0ull;

    for (int s = 0; s < 4; ++s) {
        __syncthreads();
        {   // copy 16 rows of w2 (5632 floats = 2816 u64 = 256*11)
            const unsigned long long* gsrc =
                reinterpret_cast<const unsigned long long*>(w2 + s * 5632);
            unsigned long long* sdst = reinterpret_cast<unsigned long long*>(w2s);
            #pragma unroll
            for (int r = 0; r < 11; ++r) sdst[r * BLK + t] = gsrc[r * BLK + t];
        }
        __syncthreads();
        #pragma unroll 2
        for (int jl = 0; jl < 16; ++jl) {
            int jg = s * 16 + jl;
            const unsigned long long* hp =
                reinterpret_cast<const unsigned long long*>(&hs[jg * HS_PITCH + 8 * wr]);
            unsigned long long h0 = hp[0], h1 = hp[1], h2 = hp[2], h3 = hp[3];
            #pragma unroll
            for (int p = 0; p < NPATHS; ++p) {
                unsigned long long wv = dupf(w2s[jl * NRAD + p * 32 + u]);
                fma2(acc[p][0], wv, h0);
                fma2(acc[p][1], wv, h1);
                fma2(acc[p][2], wv, h2);
                fma2(acc[p][3], wv, h3);
            }
        }
    }

    // ================= Phase D: per-edge M matrices (own warp's edges) =====
    int   md_w3j[4], md_nb[4], md_yoff[4];
    float md_pw[4];
    bool  md_v[4];
    #pragma unroll
    for (int g = 0; g < 4; ++g) {
        int idx = g * 32 + u;
        md_v[g] = (idx < 115);
        int p = 10;
        if (md_v[g]) { while (c_OFF[p] > idx) --p; } else { p = 0; }
        int r  = idx - c_OFF[p];
        int wk = 2 * c_PK[p] + 1;
        int a  = r / wk;
        int c  = r - a * wk;
        int jj = c_PJ[p];
        md_w3j[g]  = p * 125 + a * 25 + c;
        md_nb[g]   = 2 * jj + 1;
        md_yoff[g] = (jj == 0) ? -1 : ((jj == 1) ? 0 : 3);
        md_pw[g]   = c_PW[p];
    }
    for (int q = 0; q < 8; ++q) {
        int e = 8 * wr + q;
        if (cutsm[e] == 0.f) continue;      // dead edge: TP contribution is 0
        #pragma unroll
        for (int g = 0; g < 4; ++g) {
            if (!md_v[g]) continue;
            const float* wb = w3jsm + md_w3j[g];
            float a;
            if (md_yoff[g] < 0) {
                a = wb[0];
            } else {
                a = 0.f;
                for (int b = 0; b < md_nb[g]; ++b)
                    a = fmaf(wb[5 * b], ysm[e * 8 + md_yoff[g] + b], a);
            }
            Msm[e * M_PITCH + g * 32 + u] = a * md_pw[g];
        }
    }
    __syncwarp();

    // ================= Phase E: tensor product + scatter ===================
    float b2r[NPATHS];
    #pragma unroll
    for (int p = 0; p < NPATHS; ++p) b2r[p] = b2[p * 32 + u];

    #pragma unroll
    for (int q = 0; q < 8; ++q) {
        int e = 8 * wr + q;
        float cutv = cutsm[e];
        if (cutv == 0.f) continue;          // dead edge: no message, no atomics
        int sn = srcsm[e], dn = dstsm[e];
        const float* xb = nodes + (size_t)sn * FEAT;
        float x0r = xb[u];
        float x1r[3], x2r[5];
        #pragma unroll
        for (int a = 0; a < 3; ++a) x1r[a] = xb[32 + u * 3 + a];
        #pragma unroll
        for (int a = 0; a < 5; ++a) x2r[a] = xb[128 + u * 5 + a];

        float wv[NPATHS];
        #pragma unroll
        for (int p = 0; p < NPATHS; ++p) {
            unsigned long long v = acc[p][q >> 1];
            unsigned bits = (q & 1) ? (unsigned)(v >> 32) : (unsigned)v;
            wv[p] = (__uint_as_float(bits) + b2r[p]) * cutv;
        }

        const float* Mb = Msm + e * M_PITCH;
        float m0 = 0.f, m1[3] = {0.f, 0.f, 0.f}, m2[5] = {0.f, 0.f, 0.f, 0.f, 0.f};
        float s;
        // p0 (0,0,0)
        m0 = fmaf(wv[0], x0r * Mb[0], m0);
        // p1 (0,1,1)
        #pragma unroll
        for (int c = 0; c < 3; ++c) m1[c] = fmaf(wv[1], x0r * Mb[1 + c], m1[c]);
        // p2 (0,2,2)
        #pragma unroll
        for (int c = 0; c < 5; ++c) m2[c] = fmaf(wv[2], x0r * Mb[4 + c], m2[c]);
        // p3 (1,0,1)
        #pragma unroll
        for (int c = 0; c < 3; ++c) {
            s = x1r[0] * Mb[9 + c] + x1r[1] * Mb[12 + c] + x1r[2] * Mb[15 + c];
            m1[c] = fmaf(wv[3], s, m1[c]);
        }
        // p4 (1,1,0)
        s = x1r[0] * Mb[18] + x1r[1] * Mb[19] + x1r[2] * Mb[20];
        m0 = fmaf(wv[4], s, m0);
        // p5 (1,1,2)
        #pragma unroll
        for (int c = 0; c < 5; ++c) {
            s = x1r[0] * Mb[21 + c] + x1r[1] * Mb[26 + c] + x1r[2] * Mb[31 + c];
            m2[c] = fmaf(wv[5], s, m2[c]);
        }
        // p6 (1,2,1)
        #pragma unroll
        for (int c = 0; c < 3; ++c) {
            s = x1r[0] * Mb[36 + c] + x1r[1] * Mb[39 + c] + x1r[2] * Mb[42 + c];
            m1[c] = fmaf(wv[6], s, m1[c]);
        }
        // p7 (2,0,2)
        #pragma unroll
        for (int c = 0; c < 5; ++c) {
            s = 0.f;
            #pragma unroll
            for (int a = 0; a < 5; ++a) s = fmaf(x2r[a], Mb[45 + a * 5 + c], s);
            m2[c] = fmaf(wv[7], s, m2[c]);
        }
        // p8 (2,1,1)
        #pragma unroll
        for (int c = 0; c < 3; ++c) {
            s = 0.f;
            #pragma unroll
            for (int a = 0; a < 5; ++a) s = fmaf(x2r[a], Mb[70 + a * 3 + c], s);
            m1[c] = fmaf(wv[8], s, m1[c]);
        }
        // p9 (2,2,0)
        s = 0.f;
        #pragma unroll
        for (int a = 0; a < 5; ++a) s = fmaf(x2r[a], Mb[85 + a], s);
        m0 = fmaf(wv[9], s, m0);
        // p10 (2,2,2)
        #pragma unroll
        for (int c = 0; c < 5; ++c) {
            s = 0.f;
            #pragma unroll
            for (int a = 0; a < 5; ++a) s = fmaf(x2r[a], Mb[90 + a * 5 + c], s);
            m2[c] = fmaf(wv[10], s, m2[c]);
        }

        float* ob = out + (size_t)dn * FEAT;
        atomicAdd(&ob[u], m0);
        #pragma unroll
        for (int a = 0; a < 3; ++a) atomicAdd(&ob[32 + u * 3 + a], m1[a]);
        #pragma unroll
        for (int a = 0; a < 5; ++a) atomicAdd(&ob[128 + u * 5 + a], m2[a]);
    }
}

// ---------------------------------------------------------------------------
extern "C" void kernel_launch(void* const* d_in, const int* in_sizes, int n_in,
                              void* d_out, int out_size) {
    const float* nodes = (const float*)d_in[0];
    const float* pos   = (const float*)d_in[1];
    const int*   src   = (const int*)d_in[2];
    const int*   dst   = (const int*)d_in[3];
    const float* w1    = (const float*)d_in[4];
    const float* b1    = (const float*)d_in[5];
    const float* w2    = (const float*)d_in[6];
    const float* b2    = (const float*)d_in[7];
    float* out = (float*)d_out;

    setup_kernel<<<SETUP_BLOCKS, 128>>>(out, out_size / 4);

    cudaFuncSetAttribute(conv_kernel,
                         cudaFuncAttributeMaxDynamicSharedMemorySize, SMEM_BYTES);
    int nblocks = (N_EDGES + EPB - 1) / EPB;
    conv_kernel<<<nblocks, BLK, SMEM_BYTES>>>(nodes, pos, src, dst,
                                              w1, b1, w2, b2, out);
}

// round 4
// speedup vs baseline: 1.3421x; 1.1696x over previous
#include <cuda_runtime.h>
#include <cuda_bf16.h>
#include <math.h>

// ---------------------------------------------------------------------------
// Problem constants
// ---------------------------------------------------------------------------
#define N_NODES   10000
#define N_EDGES   250000
#define FF        32
#define HIDDEN    64
#define NPATHS    11
#define FEAT      288
#define NRAD      352

#define EPB       32          // edges per block
#define BLK       256         // threads per block
#define HS_PITCH  34          // padded pitch for h[j][e]
#define M_PITCH   116         // padded pitch for M[e][elem] (115 used)

// PATHS = [(0,0,0),(0,1,1),(0,2,2),(1,0,1),(1,1,0),(1,1,2),
//          (1,2,1),(2,0,2),(2,1,1),(2,2,0),(2,2,2)]
__constant__ int c_PI[NPATHS]  = {0,0,0,1,1,1,1,2,2,2,2};
__constant__ int c_PJ[NPATHS]  = {0,1,2,0,1,1,2,0,1,2,2};
__constant__ int c_PK[NPATHS]  = {0,1,2,1,0,2,1,2,1,0,2};
// element-offset of path p in the per-edge M vector; sizes (2i+1)(2k+1):
// {1,3,5,9,3,15,9,25,15,5,25} -> total 115
__constant__ int c_OFF[NPATHS] = {0,1,4,9,18,21,36,45,70,85,90};
// PATH_W[p]/sqrt(25) = sqrt((2k+1)/cnt[k])/5 ; cnt = {k0:3, k1:4, k2:4}
__constant__ float c_PW[NPATHS] = {
    0.11547005383792515f, 0.17320508075688773f, 0.22360679774997896f,
    0.17320508075688773f, 0.11547005383792515f, 0.22360679774997896f,
    0.17320508075688773f, 0.22360679774997896f, 0.17320508075688773f,
    0.11547005383792515f, 0.22360679774997896f};

// Dense padded W3J: [path][a*25 + b*5 + c] (zeros outside (2i+1,2j+1,2k+1))
__device__ float g_w3j[NPATHS * 125];

// ---------------------------------------------------------------------------
// Setup kernel: zero the output AND compute W3J (fp32 mirror of the
// reference: SU(2) CG -> complex basis change -> pick re/im by norm ->
// normalize).
// ---------------------------------------------------------------------------
__device__ __forceinline__ float ffact(int n) {
    float r = 1.0f;
    for (int i = 2; i <= n; ++i) r *= (float)i;
    return r;
}

__device__ float su2_cg_f(int j1, int j2, int j3, int m1, int m2, int m3) {
    if (m1 + m2 != m3) return 0.0f;
    float pref = sqrtf((2.0f * j3 + 1.0f) * ffact(j1 + j2 - j3) * ffact(j1 - j2 + j3) *
                       ffact(-j1 + j2 + j3) / ffact(j1 + j2 + j3 + 1));
    pref *= sqrtf(ffact(j3 + m3) * ffact(j3 - m3) * ffact(j1 - m1) * ffact(j1 + m1) *
                  ffact(j2 - m2) * ffact(j2 + m2));
    float s = 0.0f;
    for (int k = 0; k <= j1 + j2 - j3; ++k) {
        int e1 = j1 + j2 - j3 - k, e2 = j1 - m1 - k, e3 = j2 + m2 - k;
        int e4 = j3 - j2 + m1 + k, e5 = j3 - j1 - m2 + k;
        if (e1 < 0 || e2 < 0 || e3 < 0 || e4 < 0 || e5 < 0) continue;
        float term = 1.0f / (ffact(k) * ffact(e1) * ffact(e2) * ffact(e3) *
                             ffact(e4) * ffact(e5));
        s += (k & 1) ? -term : term;
    }
    return pref * s;
}

// q(l)[r][c] including the (-1j)^l prefactor
__device__ __forceinline__ void qval_f(int l, int r, int c, float& re, float& im) {
    const float is2 = 0.70710678118654752440f;
    int m = r - l;
    float a = 0.0f, b = 0.0f;
    if (m < 0) {
        if (c == l - m) a = is2;          // col l+|m|
        else if (c == l + m) b = -is2;    // col l-|m|
    } else if (m == 0) {
        if (c == l) a = 1.0f;
    } else {
        float sg = (m & 1) ? -1.0f : 1.0f;
        if (c == l + m) a = sg * is2;
        else if (c == l - m) b = sg * is2;
    }
    if (l == 1) { float ta = b, tb = -a; a = ta; b = tb; }   // *(-i)
    else if (l == 2) { a = -a; b = -b; }                      // *(-1)
    re = a; im = b;
}

#define SETUP_BLOCKS 512

__global__ void __launch_bounds__(128) setup_kernel(float* __restrict__ out, int n4) {
    // grid-stride zero of the output (float4)
    {
        float4* o4 = (float4*)out;
        float4 z = make_float4(0.f, 0.f, 0.f, 0.f);
        for (int i = blockIdx.x * blockDim.x + threadIdx.x; i < n4;
             i += gridDim.x * blockDim.x)
            o4[i] = z;
    }
    if (blockIdx.x >= NPATHS) return;

    int p = blockIdx.x, t = threadIdx.x;
    int l1 = c_PI[p], l2 = c_PJ[p], l3 = c_PK[p];
    int d1 = 2 * l1 + 1, d2 = 2 * l2 + 1, d3 = 2 * l3 + 1;
    int n = d1 * d2 * d3;
    __shared__ float C[125], Wre[125], Wim[125];
    __shared__ float sel[2];

    for (int idx = t; idx < n; idx += blockDim.x) {
        int i = idx / (d2 * d3), k = (idx / d3) % d2, m = idx % d3;
        C[idx] = su2_cg_f(l1, l2, l3, i - l1, k - l2, m - l3);
    }
    __syncthreads();

    for (int idx = t; idx < n; idx += blockDim.x) {
        int jj = idx / (d2 * d3), ll = (idx / d3) % d2, nn = idx % d3;
        float sre = 0.0f, sim = 0.0f;
        for (int i = 0; i < d1; ++i)
            for (int k = 0; k < d2; ++k)
                for (int m = 0; m < d3; ++m) {
                    float cc = C[(i * d2 + k) * d3 + m];
                    if (cc == 0.0f) continue;
                    float a1, b1, a2, b2, a3, b3;
                    qval_f(l1, i, jj, a1, b1);
                    qval_f(l2, k, ll, a2, b2);
                    qval_f(l3, m, nn, a3, b3);
                    float pr = a1 * a2 - b1 * b2;
                    float pi = a1 * b2 + b1 * a2;
                    float rr = pr * a3 + pi * b3;   // * conj(q3)
                    float ri = pi * a3 - pr * b3;
                    sre += cc * rr;
                    sim += cc * ri;
                }
        Wre[idx] = sre; Wim[idx] = sim;
    }
    __syncthreads();

    if (t == 0) {
        float nr = 0.0f, ni = 0.0f;
        for (int idx = 0; idx < n; ++idx) {
            nr += Wre[idx] * Wre[idx];
            ni += Wim[idx] * Wim[idx];
        }
        nr = sqrtf(nr); ni = sqrtf(ni);
        sel[0] = (nr >= ni) ? 1.0f : 0.0f;
        sel[1] = (nr >= ni) ? nr : ni;
    }
    __syncthreads();

    bool useRe = sel[0] > 0.5f;
    float inv = 1.0f / sel[1];
    for (int idx = t; idx < 125; idx += blockDim.x) {
        int a = idx / 25, b = (idx / 5) % 5, c = idx % 5;
        float v = 0.0f;
        if (a < d1 && b < d2 && c < d3) {
            float wv = useRe ? Wre[(a * d2 + b) * d3 + c] : Wim[(a * d2 + b) * d3 + c];
            v = wv * inv;
        }
        g_w3j[p * 125 + idx] = v;
    }
}

// ---------------------------------------------------------------------------
// packed f32x2 helpers
// ---------------------------------------------------------------------------
__device__ __forceinline__ unsigned long long dupf(float w) {
    unsigned long long r;
    unsigned u = __float_as_uint(w);
    asm("mov.b64 %0, {%1, %1};" : "=l"(r) : "r"(u));
    return r;
}
__device__ __forceinline__ void fma2(unsigned long long& d, unsigned long long a,
                                     unsigned long long b) {
    asm("fma.rn.f32x2 %0, %1, %2, %0;" : "+l"(d) : "l"(a), "l"(b));
}

// dynamic smem layout (float slots)
#define SM_W2S   0                        // 16*352 = 5632
#define SM_HS    (SM_W2S + 5632)          // HS_PITCH*64 = 2176
#define SM_MSM   (SM_HS + 2176)           // M_PITCH*32 = 3712
#define SM_YSM   (SM_MSM + 3712)          // 8*32 = 256
#define SM_BES   (SM_YSM + 256)           // 8*32 = 256
#define SM_CUT   (SM_BES + 256)           // 32
#define SM_SRC   (SM_CUT + 32)            // 32 (int)
#define SM_DST   (SM_SRC + 32)            // 32 (int)
#define SM_W3J   (SM_DST + 32)            // 1375
#define SM_TOTALF (SM_W3J + 1375)         // 13503 floats
#define SMEM_BYTES (SM_TOTALF * 4)        // 54012 B

__global__ void __launch_bounds__(BLK, 2) conv_kernel(
    const float* __restrict__ nodes, const float* __restrict__ pos,
    const int* __restrict__ src, const int* __restrict__ dst,
    const float* __restrict__ w1, const float* __restrict__ b1,
    const float* __restrict__ w2, const float* __restrict__ b2,
    float* __restrict__ out)
{
    extern __shared__ float smf[];
    float* w2s   = smf + SM_W2S;
    float* hs    = smf + SM_HS;
    float* Msm   = smf + SM_MSM;
    float* ysm   = smf + SM_YSM;
    float* bessm = smf + SM_BES;
    float* cutsm = smf + SM_CUT;
    int*   srcsm = (int*)(smf + SM_SRC);
    int*   dstsm = (int*)(smf + SM_DST);
    float* w3jsm = smf + SM_W3J;

    const int t  = threadIdx.x;
    const int u  = t & 31;       // lane == channel
    const int wr = t >> 5;       // warp 0..7 owns edges 4*wr .. 4*wr+3

    // stage W3J table into smem (1375 floats)
    #pragma unroll
    for (int r = 0; r < 6; ++r) {
        int idx = r * BLK + t;
        if (idx < NPATHS * 125) w3jsm[idx] = g_w3j[idx];
    }

    // ================= Phase A: per-edge geometry (threads 0..31) ==========
    if (t < EPB) {
        int eg = blockIdx.x * EPB + t;
        float cut = 0.f, ux = 0.f, uy = 0.f, uz = 0.f;
        int sn = 0, dn = 0;
        float besv[8];
        #pragma unroll
        for (int n = 0; n < 8; ++n) besv[n] = 0.f;
        if (eg < N_EDGES) {
            sn = src[eg]; dn = dst[eg];
            float px = pos[3 * sn]     - pos[3 * dn];
            float py = pos[3 * sn + 1] - pos[3 * dn + 1];
            float pz = pos[3 * sn + 2] - pos[3 * dn + 2];
            float d  = sqrtf(px * px + py * py + pz * pz);
            float rin = 1.0f / fmaxf(d, 1e-12f);
            ux = px * rin; uy = py * rin; uz = pz * rin;
            if (d < 4.0f) {
                float uu = d * 0.25f;
                float u2 = uu * uu, u4 = u2 * u2, u5 = u4 * uu;
                cut = 1.0f - 6.0f * u5 + 5.0f * u5 * uu;
            }
            float tt = d * 0.2f;                       // d / BESSEL_END
            if (tt > 0.0f && tt < 1.0f) {
                float cc = 0.6324555320336759f / tt;   // sqrt(2/5)/t
                #pragma unroll
                for (int n = 1; n <= 8; ++n)
                    besv[n - 1] = cc * sinf((float)n * 3.14159265358979323846f * tt);
            }
        }
        cutsm[t] = cut;
        srcsm[t] = sn; dstsm[t] = dn;
        #pragma unroll
        for (int n = 0; n < 8; ++n) bessm[t * 8 + n] = besv[n];
        // spherical harmonics
        const float s3 = 1.7320508075688772f, s15 = 3.872983346207417f;
        const float s5h = 1.118033988749895f, s15h = 1.9364916731037085f;
        ysm[t * 8 + 0] = s3 * uy;
        ysm[t * 8 + 1] = s3 * uz;
        ysm[t * 8 + 2] = s3 * ux;
        ysm[t * 8 + 3] = s15 * ux * uy;
        ysm[t * 8 + 4] = s15 * uy * uz;
        ysm[t * 8 + 5] = s5h * (3.0f * uz * uz - 1.0f);
        ysm[t * 8 + 6] = s15 * ux * uz;
        ysm[t * 8 + 7] = s15h * (ux * ux - uy * uy);
    }
    __syncthreads();

    // ================= Phase B: hidden layer h = silu(bes@w1+b1) ===========
    {
        int j   = t & 63;
        int eg0 = (t >> 6) * 8;
        float w1r[8];
        #pragma unroll
        for (int n = 0; n < 8; ++n) w1r[n] = w1[n * HIDDEN + j];
        float b1r = b1[j];
        #pragma unroll 4
        for (int ee = 0; ee < 8; ++ee) {
            int e = eg0 + ee;
            float a = b1r;
            #pragma unroll
            for (int n = 0; n < 8; ++n) a = fmaf(bessm[e * 8 + n], w1r[n], a);
            hs[j * HS_PITCH + e] = a / (1.0f + __expf(-a));   // silu
        }
    }
    // (sync folded into first GEMM stage sync)

    // ================= Phase C: GEMM h[64x32] @ w2[64x352] =================
    unsigned long long acc[NPATHS][2];
    #pragma unroll
    for (int p = 0; p < NPATHS; ++p) {
        acc[p][0] = 0ull; acc[p][1] = 0ull;
    }

    for (int s = 0; s < 4; ++s) {
        __syncthreads();
        {   // copy 16 rows of w2 (5632 floats = 2816 u64 = 256*11)
            const unsigned long long* gsrc =
                reinterpret_cast<const unsigned long long*>(w2 + s * 5632);
            unsigned long long* sdst = reinterpret_cast<unsigned long long*>(w2s);
            #pragma unroll
            for (int r = 0; r < 11; ++r) sdst[r * BLK + t] = gsrc[r * BLK + t];
        }
        __syncthreads();
        #pragma unroll 4
        for (int jl = 0; jl < 16; ++jl) {
            int jg = s * 16 + jl;
            const unsigned long long* hp =
                reinterpret_cast<const unsigned long long*>(&hs[jg * HS_PITCH + 4 * wr]);
            unsigned long long h0 = hp[0], h1 = hp[1];
            #pragma unroll
            for (int p = 0; p < NPATHS; ++p) {
                unsigned long long wv = dupf(w2s[jl * NRAD + p * 32 + u]);
                fma2(acc[p][0], wv, h0);
                fma2(acc[p][1], wv, h1);
            }
        }
    }

    // ================= Phase D: per-edge M matrices (own warp's edges) =====
    int   md_w3j[4], md_nb[4], md_yoff[4];
    float md_pw[4];
    bool  md_v[4];
    #pragma unroll
    for (int g = 0; g < 4; ++g) {
        int idx = g * 32 + u;
        md_v[g] = (idx < 115);
        int p = 10;
        if (md_v[g]) { while (c_OFF[p] > idx) --p; } else { p = 0; }
        int r  = idx - c_OFF[p];
        int wk = 2 * c_PK[p] + 1;
        int a  = r / wk;
        int c  = r - a * wk;
        int jj = c_PJ[p];
        md_w3j[g]  = p * 125 + a * 25 + c;
        md_nb[g]   = 2 * jj + 1;
        md_yoff[g] = (jj == 0) ? -1 : ((jj == 1) ? 0 : 3);
        md_pw[g]   = c_PW[p];
    }
    #pragma unroll
    for (int q = 0; q < 4; ++q) {
        int e = 4 * wr + q;
        if (cutsm[e] == 0.f) continue;      // dead edge: TP contribution is 0
        #pragma unroll
        for (int g = 0; g < 4; ++g) {
            if (!md_v[g]) continue;
            const float* wb = w3jsm + md_w3j[g];
            float a;
            if (md_yoff[g] < 0) {
                a = wb[0];
            } else {
                a = 0.f;
                for (int b = 0; b < md_nb[g]; ++b)
                    a = fmaf(wb[5 * b], ysm[e * 8 + md_yoff[g] + b], a);
            }
            Msm[e * M_PITCH + g * 32 + u] = a * md_pw[g];
        }
    }
    __syncwarp();

    // ================= Phase E: tensor product + scatter ===================
    float b2r[NPATHS];
    #pragma unroll
    for (int p = 0; p < NPATHS; ++p) b2r[p] = b2[p * 32 + u];

    #pragma unroll
    for (int q = 0; q < 4; ++q) {
        int e = 4 * wr + q;
        float cutv = cutsm[e];
        if (cutv == 0.f) continue;          // dead edge: no message, no atomics
        int sn = srcsm[e], dn = dstsm[e];
        const float* xb = nodes + (size_t)sn * FEAT;
        float x0r = xb[u];
        float x1r[3], x2r[5];
        #pragma unroll
        for (int a = 0; a < 3; ++a) x1r[a] = xb[32 + u * 3 + a];
        #pragma unroll
        for (int a = 0; a < 5; ++a) x2r[a] = xb[128 + u * 5 + a];

        float wv[NPATHS];
        #pragma unroll
        for (int p = 0; p < NPATHS; ++p) {
            unsigned long long v = acc[p][q >> 1];
            unsigned bits = (q & 1) ? (unsigned)(v >> 32) : (unsigned)v;
            wv[p] = (__uint_as_float(bits) + b2r[p]) * cutv;
        }

        const float* Mb = Msm + e * M_PITCH;
        float m0 = 0.f, m1[3] = {0.f, 0.f, 0.f}, m2[5] = {0.f, 0.f, 0.f, 0.f, 0.f};
        float s;
        // p0 (0,0,0)
        m0 = fmaf(wv[0], x0r * Mb[0], m0);
        // p1 (0,1,1)
        #pragma unroll
        for (int c = 0; c < 3; ++c) m1[c] = fmaf(wv[1], x0r * Mb[1 + c], m1[c]);
        // p2 (0,2,2)
        #pragma unroll
        for (int c = 0; c < 5; ++c) m2[c] = fmaf(wv[2], x0r * Mb[4 + c], m2[c]);
        // p3 (1,0,1)
        #pragma unroll
        for (int c = 0; c < 3; ++c) {
            s = x1r[0] * Mb[9 + c] + x1r[1] * Mb[12 + c] + x1r[2] * Mb[15 + c];
            m1[c] = fmaf(wv[3], s, m1[c]);
        }
        // p4 (1,1,0)
        s = x1r[0] * Mb[18] + x1r[1] * Mb[19] + x1r[2] * Mb[20];
        m0 = fmaf(wv[4], s, m0);
        // p5 (1,1,2)
        #pragma unroll
        for (int c = 0; c < 5; ++c) {
            s = x1r[0] * Mb[21 + c] + x1r[1] * Mb[26 + c] + x1r[2] * Mb[31 + c];
            m2[c] = fmaf(wv[5], s, m2[c]);
        }
        // p6 (1,2,1)
        #pragma unroll
        for (int c = 0; c < 3; ++c) {
            s = x1r[0] * Mb[36 + c] + x1r[1] * Mb[39 + c] + x1r[2] * Mb[42 + c];
            m1[c] = fmaf(wv[6], s, m1[c]);
        }
        // p7 (2,0,2)
        #pragma unroll
        for (int c = 0; c < 5; ++c) {
            s = 0.f;
            #pragma unroll
            for (int a = 0; a < 5; ++a) s = fmaf(x2r[a], Mb[45 + a * 5 + c], s);
            m2[c] = fmaf(wv[7], s, m2[c]);
        }
        // p8 (2,1,1)
        #pragma unroll
        for (int c = 0; c < 3; ++c) {
            s = 0.f;
            #pragma unroll
            for (int a = 0; a < 5; ++a) s = fmaf(x2r[a], Mb[70 + a * 3 + c], s);
            m1[c] = fmaf(wv[8], s, m1[c]);
        }
        // p9 (2,2,0)
        s = 0.f;
        #pragma unroll
        for (int a = 0; a < 5; ++a) s = fmaf(x2r[a], Mb[85 + a], s);
        m0 = fmaf(wv[9], s, m0);
        // p10 (2,2,2)
        #pragma unroll
        for (int c = 0; c < 5; ++c) {
            s = 0.f;
            #pragma unroll
            for (int a = 0; a < 5; ++a) s = fmaf(x2r[a], Mb[90 + a * 5 + c], s);
            m2[c] = fmaf(wv[10], s, m2[c]);
        }

        float* ob = out + (size_t)dn * FEAT;
        atomicAdd(&ob[u], m0);
        #pragma unroll
        for (int a = 0; a < 3; ++a) atomicAdd(&ob[32 + u * 3 + a], m1[a]);
        #pragma unroll
        for (int a = 0; a < 5; ++a) atomicAdd(&ob[128 + u * 5 + a], m2[a]);
    }
}

// ---------------------------------------------------------------------------
extern "C" void kernel_launch(void* const* d_in, const int* in_sizes, int n_in,
                              void* d_out, int out_size) {
    const float* nodes = (const float*)d_in[0];
    const float* pos   = (const float*)d_in[1];
    const int*   src   = (const int*)d_in[2];
    const int*   dst   = (const int*)d_in[3];
    const float* w1    = (const float*)d_in[4];
    const float* b1    = (const float*)d_in[5];
    const float* w2    = (const float*)d_in[6];
    const float* b2    = (const float*)d_in[7];
    float* out = (float*)d_out;

    setup_kernel<<<SETUP_BLOCKS, 128>>>(out, out_size / 4);

    cudaFuncSetAttribute(conv_kernel,
                         cudaFuncAttributeMaxDynamicSharedMemorySize, SMEM_BYTES);
    int nblocks = (N_EDGES + EPB - 1) / EPB;
    conv_kernel<<<nblocks, BLK, SMEM_BYTES>>>(nodes, pos, src, dst,
                                              w1, b1, w2, b2, out);
}

// round 5
// speedup vs baseline: 1.4548x; 1.0840x over previous
#include <cuda_runtime.h>
#include <cuda_bf16.h>
#include <math.h>

// ---------------------------------------------------------------------------
// Problem constants
// ---------------------------------------------------------------------------
#define N_NODES   10000
#define N_EDGES   250000
#define FF        32
#define HIDDEN    64
#define NPATHS    11
#define FEAT      288
#define NRAD      352

#define EPB       32          // edges per block
#define BLK       256         // threads per block
#define HS_PITCH  34          // padded pitch for h[j][e]
#define M_PITCH   144         // padded pitch for M[e][elem]; path blocks 16B-aligned

// PATHS = [(0,0,0),(0,1,1),(0,2,2),(1,0,1),(1,1,0),(1,1,2),
//          (1,2,1),(2,0,2),(2,1,1),(2,2,0),(2,2,2)]
__constant__ int c_PI[NPATHS]  = {0,0,0,1,1,1,1,2,2,2,2};
__constant__ int c_PJ[NPATHS]  = {0,1,2,0,1,1,2,0,1,2,2};
__constant__ int c_PK[NPATHS]  = {0,1,2,1,0,2,1,2,1,0,2};
// dense element-offset of path p (sizes {1,3,5,9,3,15,9,25,15,5,25} -> 115)
__constant__ int c_OFF[NPATHS]  = {0,1,4,9,18,21,36,45,70,85,90};
// padded (16B-aligned) offsets within the 144-float per-edge M vector
__constant__ int c_OFFP[NPATHS] = {0,4,8,16,28,32,48,60,88,104,112};
// PATH_W[p]/sqrt(25)
__constant__ float c_PW[NPATHS] = {
    0.11547005383792515f, 0.17320508075688773f, 0.22360679774997896f,
    0.17320508075688773f, 0.11547005383792515f, 0.22360679774997896f,
    0.17320508075688773f, 0.22360679774997896f, 0.17320508075688773f,
    0.11547005383792515f, 0.22360679774997896f};

// Dense padded W3J: [path][a*25 + b*5 + c]
__device__ float g_w3j[NPATHS * 125];

// ---------------------------------------------------------------------------
// Setup kernel: zero output + compute W3J (fp32 mirror of the reference).
// ---------------------------------------------------------------------------
__device__ __forceinline__ float ffact(int n) {
    float r = 1.0f;
    for (int i = 2; i <= n; ++i) r *= (float)i;
    return r;
}

__device__ float su2_cg_f(int j1, int j2, int j3, int m1, int m2, int m3) {
    if (m1 + m2 != m3) return 0.0f;
    float pref = sqrtf((2.0f * j3 + 1.0f) * ffact(j1 + j2 - j3) * ffact(j1 - j2 + j3) *
                       ffact(-j1 + j2 + j3) / ffact(j1 + j2 + j3 + 1));
    pref *= sqrtf(ffact(j3 + m3) * ffact(j3 - m3) * ffact(j1 - m1) * ffact(j1 + m1) *
                  ffact(j2 - m2) * ffact(j2 + m2));
    float s = 0.0f;
    for (int k = 0; k <= j1 + j2 - j3; ++k) {
        int e1 = j1 + j2 - j3 - k, e2 = j1 - m1 - k, e3 = j2 + m2 - k;
        int e4 = j3 - j2 + m1 + k, e5 = j3 - j1 - m2 + k;
        if (e1 < 0 || e2 < 0 || e3 < 0 || e4 < 0 || e5 < 0) continue;
        float term = 1.0f / (ffact(k) * ffact(e1) * ffact(e2) * ffact(e3) *
                             ffact(e4) * ffact(e5));
        s += (k & 1) ? -term : term;
    }
    return pref * s;
}

__device__ __forceinline__ void qval_f(int l, int r, int c, float& re, float& im) {
    const float is2 = 0.70710678118654752440f;
    int m = r - l;
    float a = 0.0f, b = 0.0f;
    if (m < 0) {
        if (c == l - m) a = is2;
        else if (c == l + m) b = -is2;
    } else if (m == 0) {
        if (c == l) a = 1.0f;
    } else {
        float sg = (m & 1) ? -1.0f : 1.0f;
        if (c == l + m) a = sg * is2;
        else if (c == l - m) b = sg * is2;
    }
    if (l == 1) { float ta = b, tb = -a; a = ta; b = tb; }   // *(-i)
    else if (l == 2) { a = -a; b = -b; }                      // *(-1)
    re = a; im = b;
}

#define SETUP_BLOCKS 512

__global__ void __launch_bounds__(128) setup_kernel(float* __restrict__ out, int n4) {
    {
        float4* o4 = (float4*)out;
        float4 z = make_float4(0.f, 0.f, 0.f, 0.f);
        for (int i = blockIdx.x * blockDim.x + threadIdx.x; i < n4;
             i += gridDim.x * blockDim.x)
            o4[i] = z;
    }
    if (blockIdx.x >= NPATHS) return;

    int p = blockIdx.x, t = threadIdx.x;
    int l1 = c_PI[p], l2 = c_PJ[p], l3 = c_PK[p];
    int d1 = 2 * l1 + 1, d2 = 2 * l2 + 1, d3 = 2 * l3 + 1;
    int n = d1 * d2 * d3;
    __shared__ float C[125], Wre[125], Wim[125];
    __shared__ float sel[2];

    for (int idx = t; idx < n; idx += blockDim.x) {
        int i = idx / (d2 * d3), k = (idx / d3) % d2, m = idx % d3;
        C[idx] = su2_cg_f(l1, l2, l3, i - l1, k - l2, m - l3);
    }
    __syncthreads();

    for (int idx = t; idx < n; idx += blockDim.x) {
        int jj = idx / (d2 * d3), ll = (idx / d3) % d2, nn = idx % d3;
        float sre = 0.0f, sim = 0.0f;
        for (int i = 0; i < d1; ++i)
            for (int k = 0; k < d2; ++k)
                for (int m = 0; m < d3; ++m) {
                    float cc = C[(i * d2 + k) * d3 + m];
                    if (cc == 0.0f) continue;
                    float a1, b1, a2, b2, a3, b3;
                    qval_f(l1, i, jj, a1, b1);
                    qval_f(l2, k, ll, a2, b2);
                    qval_f(l3, m, nn, a3, b3);
                    float pr = a1 * a2 - b1 * b2;
                    float pi = a1 * b2 + b1 * a2;
                    float rr = pr * a3 + pi * b3;
                    float ri = pi * a3 - pr * b3;
                    sre += cc * rr;
                    sim += cc * ri;
                }
        Wre[idx] = sre; Wim[idx] = sim;
    }
    __syncthreads();

    if (t == 0) {
        float nr = 0.0f, ni = 0.0f;
        for (int idx = 0; idx < n; ++idx) {
            nr += Wre[idx] * Wre[idx];
            ni += Wim[idx] * Wim[idx];
        }
        nr = sqrtf(nr); ni = sqrtf(ni);
        sel[0] = (nr >= ni) ? 1.0f : 0.0f;
        sel[1] = (nr >= ni) ? nr : ni;
    }
    __syncthreads();

    bool useRe = sel[0] > 0.5f;
    float inv = 1.0f / sel[1];
    for (int idx = t; idx < 125; idx += blockDim.x) {
        int a = idx / 25, b = (idx / 5) % 5, c = idx % 5;
        float v = 0.0f;
        if (a < d1 && b < d2 && c < d3) {
            float wv = useRe ? Wre[(a * d2 + b) * d3 + c] : Wim[(a * d2 + b) * d3 + c];
            v = wv * inv;
        }
        g_w3j[p * 125 + idx] = v;
    }
}

// ---------------------------------------------------------------------------
// packed f32x2 helpers
// ---------------------------------------------------------------------------
__device__ __forceinline__ unsigned long long dupf(float w) {
    unsigned long long r;
    unsigned u = __float_as_uint(w);
    asm("mov.b64 %0, {%1, %1};" : "=l"(r) : "r"(u));
    return r;
}
__device__ __forceinline__ void fma2(unsigned long long& d, unsigned long long a,
                                     unsigned long long b) {
    asm("fma.rn.f32x2 %0, %1, %2, %0;" : "+l"(d) : "l"(a), "l"(b));
}
__device__ __forceinline__ void red4(float* p, float a, float b, float c, float d) {
    asm volatile("red.global.add.v4.f32 [%0], {%1, %2, %3, %4};"
                 :: "l"(p), "f"(a), "f"(b), "f"(c), "f"(d) : "memory");
}

// dynamic smem layout (float slots)
#define SM_W2S   0                        // 16*352 = 5632
#define SM_HS    (SM_W2S + 5632)          // 34*64 = 2176
#define SM_MSM   (SM_HS + 2176)           // 144*32 = 4608  (16B aligned: 7808%4==0)
#define SM_YSM   (SM_MSM + 4608)          // 8*32 = 256
#define SM_BES   (SM_YSM + 256)           // 8*32 = 256
#define SM_CUT   (SM_BES + 256)           // 32
#define SM_SRC   (SM_CUT + 32)            // 32 (int)
#define SM_DST   (SM_SRC + 32)            // 32 (int)
#define SM_MSG   (SM_DST + 32)            // 8*296 = 2368 (13024%4==0 -> 16B)
#define SM_W3J   (SM_MSG + 2368)          // 1375
#define SM_TOTALF (SM_W3J + 1375)         // 16767 floats
#define SMEM_BYTES (SM_TOTALF * 4)        // 67068 B

__global__ void __launch_bounds__(BLK, 2) conv_kernel(
    const float* __restrict__ nodes, const float* __restrict__ pos,
    const int* __restrict__ src, const int* __restrict__ dst,
    const float* __restrict__ w1, const float* __restrict__ b1,
    const float* __restrict__ w2, const float* __restrict__ b2,
    float* __restrict__ out)
{
    extern __shared__ float smf[];
    float* w2s   = smf + SM_W2S;
    float* hs    = smf + SM_HS;
    float* Msm   = smf + SM_MSM;
    float* ysm   = smf + SM_YSM;
    float* bessm = smf + SM_BES;
    float* cutsm = smf + SM_CUT;
    int*   srcsm = (int*)(smf + SM_SRC);
    int*   dstsm = (int*)(smf + SM_DST);
    float* w3jsm = smf + SM_W3J;

    const int t  = threadIdx.x;
    const int u  = t & 31;       // lane == channel
    const int wr = t >> 5;       // warp 0..7 owns edges 4*wr .. 4*wr+3
    float* msgw = smf + SM_MSG + wr * 296;

    // stage W3J table into smem (1375 floats)
    #pragma unroll
    for (int r = 0; r < 6; ++r) {
        int idx = r * BLK + t;
        if (idx < NPATHS * 125) w3jsm[idx] = g_w3j[idx];
    }

    // ================= Phase A: per-edge geometry (threads 0..31) ==========
    if (t < EPB) {
        int eg = blockIdx.x * EPB + t;
        float cut = 0.f, ux = 0.f, uy = 0.f, uz = 0.f;
        int sn = 0, dn = 0;
        float besv[8];
        #pragma unroll
        for (int n = 0; n < 8; ++n) besv[n] = 0.f;
        if (eg < N_EDGES) {
            sn = src[eg]; dn = dst[eg];
            float px = pos[3 * sn]     - pos[3 * dn];
            float py = pos[3 * sn + 1] - pos[3 * dn + 1];
            float pz = pos[3 * sn + 2] - pos[3 * dn + 2];
            float d  = sqrtf(px * px + py * py + pz * pz);
            float rin = 1.0f / fmaxf(d, 1e-12f);
            ux = px * rin; uy = py * rin; uz = pz * rin;
            if (d < 4.0f) {
                float uu = d * 0.25f;
                float u2 = uu * uu, u4 = u2 * u2, u5 = u4 * uu;
                cut = 1.0f - 6.0f * u5 + 5.0f * u5 * uu;
            }
            float tt = d * 0.2f;                       // d / BESSEL_END
            if (tt > 0.0f && tt < 1.0f) {
                float cc = 0.6324555320336759f / tt;   // sqrt(2/5)/t
                #pragma unroll
                for (int n = 1; n <= 8; ++n)
                    besv[n - 1] = cc * sinf((float)n * 3.14159265358979323846f * tt);
            }
        }
        cutsm[t] = cut;
        srcsm[t] = sn; dstsm[t] = dn;
        #pragma unroll
        for (int n = 0; n < 8; ++n) bessm[t * 8 + n] = besv[n];
        const float s3 = 1.7320508075688772f, s15 = 3.872983346207417f;
        const float s5h = 1.118033988749895f, s15h = 1.9364916731037085f;
        ysm[t * 8 + 0] = s3 * uy;
        ysm[t * 8 + 1] = s3 * uz;
        ysm[t * 8 + 2] = s3 * ux;
        ysm[t * 8 + 3] = s15 * ux * uy;
        ysm[t * 8 + 4] = s15 * uy * uz;
        ysm[t * 8 + 5] = s5h * (3.0f * uz * uz - 1.0f);
        ysm[t * 8 + 6] = s15 * ux * uz;
        ysm[t * 8 + 7] = s15h * (ux * ux - uy * uy);
    }
    __syncthreads();

    // ================= Phase B: hidden layer h = silu(bes@w1+b1) ===========
    {
        int j   = t & 63;
        int eg0 = (t >> 6) * 8;
        float w1r[8];
        #pragma unroll
        for (int n = 0; n < 8; ++n) w1r[n] = w1[n * HIDDEN + j];
        float b1r = b1[j];
        #pragma unroll 4
        for (int ee = 0; ee < 8; ++ee) {
            int e = eg0 + ee;
            float a = b1r;
            #pragma unroll
            for (int n = 0; n < 8; ++n) a = fmaf(bessm[e * 8 + n], w1r[n], a);
            hs[j * HS_PITCH + e] = a / (1.0f + __expf(-a));   // silu
        }
    }

    // ================= Phase C: GEMM h[64x32] @ w2[64x352] =================
    unsigned long long acc[NPATHS][2];
    #pragma unroll
    for (int p = 0; p < NPATHS; ++p) {
        acc[p][0] = 0ull; acc[p][1] = 0ull;
    }

    for (int s = 0; s < 4; ++s) {
        __syncthreads();
        {   // copy 16 rows of w2 (5632 floats = 2816 u64 = 256*11)
            const unsigned long long* gsrc =
                reinterpret_cast<const unsigned long long*>(w2 + s * 5632);
            unsigned long long* sdst = reinterpret_cast<unsigned long long*>(w2s);
            #pragma unroll
            for (int r = 0; r < 11; ++r) sdst[r * BLK + t] = gsrc[r * BLK + t];
        }
        __syncthreads();
        #pragma unroll 4
        for (int jl = 0; jl < 16; ++jl) {
            int jg = s * 16 + jl;
            const unsigned long long* hp =
                reinterpret_cast<const unsigned long long*>(&hs[jg * HS_PITCH + 4 * wr]);
            unsigned long long h0 = hp[0], h1 = hp[1];
            #pragma unroll
            for (int p = 0; p < NPATHS; ++p) {
                unsigned long long wv = dupf(w2s[jl * NRAD + p * 32 + u]);
                fma2(acc[p][0], wv, h0);
                fma2(acc[p][1], wv, h1);
            }
        }
    }

    // ================= Phase D: per-edge M matrices (padded layout) ========
    int   md_w3j[4], md_nb[4], md_yoff[4], md_pos[4];
    float md_pw[4];
    bool  md_v[4];
    #pragma unroll
    for (int g = 0; g < 4; ++g) {
        int idx = g * 32 + u;
        md_v[g] = (idx < 115);
        int p = 10;
        if (md_v[g]) { while (c_OFF[p] > idx) --p; } else { p = 0; }
        int r  = idx - c_OFF[p];
        int wk = 2 * c_PK[p] + 1;
        int a  = r / wk;
        int c  = r - a * wk;
        int jj = c_PJ[p];
        md_w3j[g]  = p * 125 + a * 25 + c;
        md_nb[g]   = 2 * jj + 1;
        md_yoff[g] = (jj == 0) ? -1 : ((jj == 1) ? 0 : 3);
        md_pw[g]   = c_PW[p];
        md_pos[g]  = c_OFFP[p] + r;
    }
    #pragma unroll
    for (int q = 0; q < 4; ++q) {
        int e = 4 * wr + q;
        if (cutsm[e] == 0.f) continue;      // dead edge (warp-uniform)
        #pragma unroll
        for (int g = 0; g < 4; ++g) {
            if (!md_v[g]) continue;
            const float* wb = w3jsm + md_w3j[g];
            float a;
            if (md_yoff[g] < 0) {
                a = wb[0];
            } else {
                a = 0.f;
                for (int b = 0; b < md_nb[g]; ++b)
                    a = fmaf(wb[5 * b], ysm[e * 8 + md_yoff[g] + b], a);
            }
            Msm[e * M_PITCH + md_pos[g]] = a * md_pw[g];
        }
    }
    __syncwarp();

    // ================= Phase E: tensor product + vectorized scatter ========
    float b2r[NPATHS];
    #pragma unroll
    for (int p = 0; p < NPATHS; ++p) b2r[p] = b2[p * 32 + u];

    #pragma unroll
    for (int q = 0; q < 4; ++q) {
        int e = 4 * wr + q;
        float cutv = cutsm[e];
        if (cutv == 0.f) continue;          // warp-uniform skip
        int sn = srcsm[e], dn = dstsm[e];
        const float* xb = nodes + (size_t)sn * FEAT;
        float x0r = xb[u];
        float x1r[3], x2r[5];
        #pragma unroll
        for (int a = 0; a < 3; ++a) x1r[a] = xb[32 + u * 3 + a];
        #pragma unroll
        for (int a = 0; a < 5; ++a) x2r[a] = xb[128 + u * 5 + a];

        float wv[NPATHS];
        #pragma unroll
        for (int p = 0; p < NPATHS; ++p) {
            unsigned long long v = acc[p][q >> 1];
            unsigned bits = (q & 1) ? (unsigned)(v >> 32) : (unsigned)v;
            wv[p] = (__uint_as_float(bits) + b2r[p]) * cutv;
        }

        const float4* M4 = reinterpret_cast<const float4*>(Msm + e * M_PITCH);
        float m0 = 0.f, m1[3] = {0.f, 0.f, 0.f}, m2[5] = {0.f, 0.f, 0.f, 0.f, 0.f};
        float s;

        {   // S1: floats 0..31 -> p0..p4
            float A[32];
            #pragma unroll
            for (int i = 0; i < 8; ++i)
                *reinterpret_cast<float4*>(&A[4 * i]) = M4[i];
            // p0 (0,0,0) @0
            m0 = fmaf(wv[0], x0r * A[0], m0);
            // p1 (0,1,1) @4
            #pragma unroll
            for (int c = 0; c < 3; ++c) m1[c] = fmaf(wv[1], x0r * A[4 + c], m1[c]);
            // p2 (0,2,2) @8
            #pragma unroll
            for (int c = 0; c < 5; ++c) m2[c] = fmaf(wv[2], x0r * A[8 + c], m2[c]);
            // p3 (1,0,1) @16 rows 16,19,22
            #pragma unroll
            for (int c = 0; c < 3; ++c) {
                s = x1r[0] * A[16 + c] + x1r[1] * A[19 + c] + x1r[2] * A[22 + c];
                m1[c] = fmaf(wv[3], s, m1[c]);
            }
            // p4 (1,1,0) @28
            s = x1r[0] * A[28] + x1r[1] * A[29] + x1r[2] * A[30];
            m0 = fmaf(wv[4], s, m0);
        }
        {   // S2: floats 32..59 -> p5, p6
            float A[28];
            #pragma unroll
            for (int i = 0; i < 7; ++i)
                *reinterpret_cast<float4*>(&A[4 * i]) = M4[8 + i];
            // p5 (1,1,2) @32: A[a*5+c]
            #pragma unroll
            for (int c = 0; c < 5; ++c) {
                s = x1r[0] * A[c] + x1r[1] * A[5 + c] + x1r[2] * A[10 + c];
                m2[c] = fmaf(wv[5], s, m2[c]);
            }
            // p6 (1,2,1) @48: A[16 + a*3 + c]
            #pragma unroll
            for (int c = 0; c < 3; ++c) {
                s = x1r[0] * A[16 + c] + x1r[1] * A[19 + c] + x1r[2] * A[22 + c];
                m1[c] = fmaf(wv[6], s, m1[c]);
            }
        }
        {   // S3: floats 60..87 -> p7 (2,0,2) @60: A[a*5+c]
            float A[28];
            #pragma unroll
            for (int i = 0; i < 7; ++i)
                *reinterpret_cast<float4*>(&A[4 * i]) = M4[15 + i];
            #pragma unroll
            for (int c = 0; c < 5; ++c) {
                s = 0.f;
                #pragma unroll
                for (int a = 0; a < 5; ++a) s = fmaf(x2r[a], A[a * 5 + c], s);
                m2[c] = fmaf(wv[7], s, m2[c]);
            }
        }
        {   // S4: floats 88..111 -> p8 @88 (A[a*3+c]), p9 @104 (A[16+a])
            float A[24];
            #pragma unroll
            for (int i = 0; i < 6; ++i)
                *reinterpret_cast<float4*>(&A[4 * i]) = M4[22 + i];
            #pragma unroll
            for (int c = 0; c < 3; ++c) {
                s = 0.f;
                #pragma unroll
                for (int a = 0; a < 5; ++a) s = fmaf(x2r[a], A[a * 3 + c], s);
                m1[c] = fmaf(wv[8], s, m1[c]);
            }
            s = 0.f;
            #pragma unroll
            for (int a = 0; a < 5; ++a) s = fmaf(x2r[a], A[16 + a], s);
            m0 = fmaf(wv[9], s, m0);
        }
        {   // S5: floats 112..136 -> p10 (2,2,2) @112: A[a*5+c]
            float A[28];
            #pragma unroll
            for (int i = 0; i < 7; ++i)
                *reinterpret_cast<float4*>(&A[4 * i]) = M4[28 + i];
            #pragma unroll
            for (int c = 0; c < 5; ++c) {
                s = 0.f;
                #pragma unroll
                for (int a = 0; a < 5; ++a) s = fmaf(x2r[a], A[a * 5 + c], s);
                m2[c] = fmaf(wv[10], s, m2[c]);
            }
        }

        // stage message in out-layout order, then vectorized atomic scatter
        msgw[u] = m0;
        #pragma unroll
        for (int a = 0; a < 3; ++a) msgw[32 + u * 3 + a] = m1[a];
        #pragma unroll
        for (int a = 0; a < 5; ++a) msgw[128 + u * 5 + a] = m2[a];
        __syncwarp();

        float* ob = out + (size_t)dn * FEAT;
        const float4* mg4 = reinterpret_cast<const float4*>(msgw);
        {
            float4 v0 = mg4[u];
            red4(ob + 4 * u, v0.x, v0.y, v0.z, v0.w);
            float4 v1 = mg4[u + 32];
            red4(ob + 4 * (u + 32), v1.x, v1.y, v1.z, v1.w);
            if (u < 8) {
                float4 v2 = mg4[u + 64];
                red4(ob + 4 * (u + 64), v2.x, v2.y, v2.z, v2.w);
            }
        }
        __syncwarp();
    }
}

// ---------------------------------------------------------------------------
extern "C" void kernel_launch(void* const* d_in, const int* in_sizes, int n_in,
                              void* d_out, int out_size) {
    const float* nodes = (const float*)d_in[0];
    const float* pos   = (const float*)d_in[1];
    const int*   src   = (const int*)d_in[2];
    const int*   dst   = (const int*)d_in[3];
    const float* w1    = (const float*)d_in[4];
    const float* b1    = (const float*)d_in[5];
    const float* w2    = (const float*)d_in[6];
    const float* b2    = (const float*)d_in[7];
    float* out = (float*)d_out;

    setup_kernel<<<SETUP_BLOCKS, 128>>>(out, out_size / 4);

    cudaFuncSetAttribute(conv_kernel,
                         cudaFuncAttributeMaxDynamicSharedMemorySize, SMEM_BYTES);
    int nblocks = (N_EDGES + EPB - 1) / EPB;
    conv_kernel<<<nblocks, BLK, SMEM_BYTES>>>(nodes, pos, src, dst,
                                              w1, b1, w2, b2, out);
}

// round 6
// speedup vs baseline: 1.8269x; 1.2558x over previous
#include <cuda_runtime.h>
#include <cuda_bf16.h>
#include <math.h>

// ---------------------------------------------------------------------------
// Problem constants
// ---------------------------------------------------------------------------
#define N_NODES   10000
#define N_EDGES   250000
#define FF        32
#define HIDDEN    64
#define NPATHS    11
#define FEAT      288
#define NRAD      352

#define EPB       32          // edges per block
#define BLK       256         // threads per block
#define M_PITCH   144         // padded pitch for M[e][elem]; path blocks 16B-aligned

#define RTAB_N    8192        // intervals over d in [0,4]
#define RTAB_ROWS (RTAB_N + 1)

// PATHS = [(0,0,0),(0,1,1),(0,2,2),(1,0,1),(1,1,0),(1,1,2),
//          (1,2,1),(2,0,2),(2,1,1),(2,2,0),(2,2,2)]
__constant__ int c_PI[NPATHS]  = {0,0,0,1,1,1,1,2,2,2,2};
__constant__ int c_PJ[NPATHS]  = {0,1,2,0,1,1,2,0,1,2,2};
__constant__ int c_PK[NPATHS]  = {0,1,2,1,0,2,1,2,1,0,2};
// dense element-offset of path p (sizes {1,3,5,9,3,15,9,25,15,5,25} -> 115)
__constant__ int c_OFF[NPATHS]  = {0,1,4,9,18,21,36,45,70,85,90};
// padded (16B-aligned) offsets within the 144-float per-edge M vector
__constant__ int c_OFFP[NPATHS] = {0,4,8,16,28,32,48,60,88,104,112};
// PATH_W[p]/sqrt(25)
__constant__ float c_PW[NPATHS] = {
    0.11547005383792515f, 0.17320508075688773f, 0.22360679774997896f,
    0.17320508075688773f, 0.11547005383792515f, 0.22360679774997896f,
    0.17320508075688773f, 0.22360679774997896f, 0.17320508075688773f,
    0.11547005383792515f, 0.22360679774997896f};

// Dense padded W3J: [path][a*25 + b*5 + c]
__device__ float g_w3j[NPATHS * 125];
// Radial lookup table: radial_raw(d) = silu(bessel(d)@w1+b1)@w2 + b2
__device__ float g_rtab[RTAB_ROWS * NRAD];   // 11.5 MB static scratch

// ---------------------------------------------------------------------------
// Setup kernel: zero output + compute W3J (fp32 mirror of the reference).
// ---------------------------------------------------------------------------
__device__ __forceinline__ float ffact(int n) {
    float r = 1.0f;
    for (int i = 2; i <= n; ++i) r *= (float)i;
    return r;
}

__device__ float su2_cg_f(int j1, int j2, int j3, int m1, int m2, int m3) {
    if (m1 + m2 != m3) return 0.0f;
    float pref = sqrtf((2.0f * j3 + 1.0f) * ffact(j1 + j2 - j3) * ffact(j1 - j2 + j3) *
                       ffact(-j1 + j2 + j3) / ffact(j1 + j2 + j3 + 1));
    pref *= sqrtf(ffact(j3 + m3) * ffact(j3 - m3) * ffact(j1 - m1) * ffact(j1 + m1) *
                  ffact(j2 - m2) * ffact(j2 + m2));
    float s = 0.0f;
    for (int k = 0; k <= j1 + j2 - j3; ++k) {
        int e1 = j1 + j2 - j3 - k, e2 = j1 - m1 - k, e3 = j2 + m2 - k;
        int e4 = j3 - j2 + m1 + k, e5 = j3 - j1 - m2 + k;
        if (e1 < 0 || e2 < 0 || e3 < 0 || e4 < 0 || e5 < 0) continue;
        float term = 1.0f / (ffact(k) * ffact(e1) * ffact(e2) * ffact(e3) *
                             ffact(e4) * ffact(e5));
        s += (k & 1) ? -term : term;
    }
    return pref * s;
}

__device__ __forceinline__ void qval_f(int l, int r, int c, float& re, float& im) {
    const float is2 = 0.70710678118654752440f;
    int m = r - l;
    float a = 0.0f, b = 0.0f;
    if (m < 0) {
        if (c == l - m) a = is2;
        else if (c == l + m) b = -is2;
    } else if (m == 0) {
        if (c == l) a = 1.0f;
    } else {
        float sg = (m & 1) ? -1.0f : 1.0f;
        if (c == l + m) a = sg * is2;
        else if (c == l - m) b = sg * is2;
    }
    if (l == 1) { float ta = b, tb = -a; a = ta; b = tb; }   // *(-i)
    else if (l == 2) { a = -a; b = -b; }                      // *(-1)
    re = a; im = b;
}

#define SETUP_BLOCKS 512

__global__ void __launch_bounds__(128) setup_kernel(float* __restrict__ out, int n4) {
    {
        float4* o4 = (float4*)out;
        float4 z = make_float4(0.f, 0.f, 0.f, 0.f);
        for (int i = blockIdx.x * blockDim.x + threadIdx.x; i < n4;
             i += gridDim.x * blockDim.x)
            o4[i] = z;
    }
    if (blockIdx.x >= NPATHS) return;

    int p = blockIdx.x, t = threadIdx.x;
    int l1 = c_PI[p], l2 = c_PJ[p], l3 = c_PK[p];
    int d1 = 2 * l1 + 1, d2 = 2 * l2 + 1, d3 = 2 * l3 + 1;
    int n = d1 * d2 * d3;
    __shared__ float C[125], Wre[125], Wim[125];
    __shared__ float sel[2];

    for (int idx = t; idx < n; idx += blockDim.x) {
        int i = idx / (d2 * d3), k = (idx / d3) % d2, m = idx % d3;
        C[idx] = su2_cg_f(l1, l2, l3, i - l1, k - l2, m - l3);
    }
    __syncthreads();

    for (int idx = t; idx < n; idx += blockDim.x) {
        int jj = idx / (d2 * d3), ll = (idx / d3) % d2, nn = idx % d3;
        float sre = 0.0f, sim = 0.0f;
        for (int i = 0; i < d1; ++i)
            for (int k = 0; k < d2; ++k)
                for (int m = 0; m < d3; ++m) {
                    float cc = C[(i * d2 + k) * d3 + m];
                    if (cc == 0.0f) continue;
                    float a1, b1, a2, b2, a3, b3;
                    qval_f(l1, i, jj, a1, b1);
                    qval_f(l2, k, ll, a2, b2);
                    qval_f(l3, m, nn, a3, b3);
                    float pr = a1 * a2 - b1 * b2;
                    float pi = a1 * b2 + b1 * a2;
                    float rr = pr * a3 + pi * b3;
                    float ri = pi * a3 - pr * b3;
                    sre += cc * rr;
                    sim += cc * ri;
                }
        Wre[idx] = sre; Wim[idx] = sim;
    }
    __syncthreads();

    if (t == 0) {
        float nr = 0.0f, ni = 0.0f;
        for (int idx = 0; idx < n; ++idx) {
            nr += Wre[idx] * Wre[idx];
            ni += Wim[idx] * Wim[idx];
        }
        nr = sqrtf(nr); ni = sqrtf(ni);
        sel[0] = (nr >= ni) ? 1.0f : 0.0f;
        sel[1] = (nr >= ni) ? nr : ni;
    }
    __syncthreads();

    bool useRe = sel[0] > 0.5f;
    float inv = 1.0f / sel[1];
    for (int idx = t; idx < 125; idx += blockDim.x) {
        int a = idx / 25, b = (idx / 5) % 5, c = idx % 5;
        float v = 0.0f;
        if (a < d1 && b < d2 && c < d3) {
            float wv = useRe ? Wre[(a * d2 + b) * d3 + c] : Wim[(a * d2 + b) * d3 + c];
            v = wv * inv;
        }
        g_w3j[p * 125 + idx] = v;
    }
}

// ---------------------------------------------------------------------------
// Radial table build: row i = radial_raw(d_i), d_i = i * 4/8192.
// Mirrors the reference MLP exactly (bessel mask, silu, biases).
// ---------------------------------------------------------------------------
__global__ void __launch_bounds__(128) rtab_kernel(
    const float* __restrict__ w1, const float* __restrict__ b1,
    const float* __restrict__ w2, const float* __restrict__ b2)
{
    __shared__ float h[HIDDEN];
    int i = blockIdx.x;
    int t = threadIdx.x;
    float d = (float)i * (4.0f / (float)RTAB_N);

    if (t < HIDDEN) {
        float tt = d * 0.2f;                           // d / BESSEL_END
        float a = b1[t];
        if (tt > 0.0f && tt < 1.0f) {
            float cc = 0.6324555320336759f / tt;       // sqrt(2/5)/t
            #pragma unroll
            for (int n = 1; n <= 8; ++n) {
                float bv = cc * sinf((float)n * 3.14159265358979323846f * tt);
                a = fmaf(bv, w1[(n - 1) * HIDDEN + t], a);
            }
        }
        h[t] = a / (1.0f + __expf(-a));                // silu
    }
    __syncthreads();

    for (int r = t; r < NRAD; r += 128) {
        float s = b2[r];
        #pragma unroll 8
        for (int j = 0; j < HIDDEN; ++j) s = fmaf(h[j], w2[j * NRAD + r], s);
        g_rtab[i * NRAD + r] = s;
    }
}

// ---------------------------------------------------------------------------
__device__ __forceinline__ void red4(float* p, float a, float b, float c, float d) {
    asm volatile("red.global.add.v4.f32 [%0], {%1, %2, %3, %4};"
                 :: "l"(p), "f"(a), "f"(b), "f"(c), "f"(d) : "memory");
}

// dynamic smem layout (float slots); MSM and MSG are 16B-aligned
#define SM_MSM   0                        // 144*32 = 4608
#define SM_YSM   4608                     // 8*32 = 256
#define SM_MSG   4864                     // 8*296 = 2368
#define SM_W3J   (SM_MSG + 2368)          // 1375
#define SM_CUT   (SM_W3J + 1375)          // 32
#define SM_DIST  (SM_CUT + 32)            // 32
#define SM_SRC   (SM_DIST + 32)           // 32 (int)
#define SM_DST   (SM_SRC + 32)            // 32 (int)
#define SM_TOTALF (SM_DST + 32)           // 8799 floats
#define SMEM_BYTES (SM_TOTALF * 4)        // 35196 B

__global__ void __launch_bounds__(BLK, 3) conv_kernel(
    const float* __restrict__ nodes, const float* __restrict__ pos,
    const int* __restrict__ src, const int* __restrict__ dst,
    float* __restrict__ out)
{
    extern __shared__ float smf[];
    float* Msm   = smf + SM_MSM;
    float* ysm   = smf + SM_YSM;
    float* w3jsm = smf + SM_W3J;
    float* cutsm = smf + SM_CUT;
    float* distsm= smf + SM_DIST;
    int*   srcsm = (int*)(smf + SM_SRC);
    int*   dstsm = (int*)(smf + SM_DST);

    const int t  = threadIdx.x;
    const int u  = t & 31;       // lane == channel
    const int wr = t >> 5;       // warp 0..7 owns edges 4*wr .. 4*wr+3
    float* msgw = smf + SM_MSG + wr * 296;

    // stage W3J table into smem (1375 floats)
    #pragma unroll
    for (int r = 0; r < 6; ++r) {
        int idx = r * BLK + t;
        if (idx < NPATHS * 125) w3jsm[idx] = g_w3j[idx];
    }

    // ================= Phase A: per-edge geometry (threads 0..31) ==========
    if (t < EPB) {
        int eg = blockIdx.x * EPB + t;
        float cut = 0.f, ux = 0.f, uy = 0.f, uz = 0.f, d = 0.f;
        int sn = 0, dn = 0;
        if (eg < N_EDGES) {
            sn = src[eg]; dn = dst[eg];
            float px = pos[3 * sn]     - pos[3 * dn];
            float py = pos[3 * sn + 1] - pos[3 * dn + 1];
            float pz = pos[3 * sn + 2] - pos[3 * dn + 2];
            d = sqrtf(px * px + py * py + pz * pz);
            float rin = 1.0f / fmaxf(d, 1e-12f);
            ux = px * rin; uy = py * rin; uz = pz * rin;
            if (d < 4.0f) {
                float uu = d * 0.25f;
                float u2 = uu * uu, u4 = u2 * u2, u5 = u4 * uu;
                cut = 1.0f - 6.0f * u5 + 5.0f * u5 * uu;
            }
        }
        cutsm[t] = cut;
        distsm[t] = d;
        srcsm[t] = sn; dstsm[t] = dn;
        const float s3 = 1.7320508075688772f, s15 = 3.872983346207417f;
        const float s5h = 1.118033988749895f, s15h = 1.9364916731037085f;
        ysm[t * 8 + 0] = s3 * uy;
        ysm[t * 8 + 1] = s3 * uz;
        ysm[t * 8 + 2] = s3 * ux;
        ysm[t * 8 + 3] = s15 * ux * uy;
        ysm[t * 8 + 4] = s15 * uy * uz;
        ysm[t * 8 + 5] = s5h * (3.0f * uz * uz - 1.0f);
        ysm[t * 8 + 6] = s15 * ux * uz;
        ysm[t * 8 + 7] = s15h * (ux * ux - uy * uy);
    }
    __syncthreads();

    // ================= Phase D: per-edge M matrices (padded layout) ========
    int   md_w3j[4], md_nb[4], md_yoff[4], md_pos[4];
    float md_pw[4];
    bool  md_v[4];
    #pragma unroll
    for (int g = 0; g < 4; ++g) {
        int idx = g * 32 + u;
        md_v[g] = (idx < 115);
        int p = 10;
        if (md_v[g]) { while (c_OFF[p] > idx) --p; } else { p = 0; }
        int r  = idx - c_OFF[p];
        int wk = 2 * c_PK[p] + 1;
        int a  = r / wk;
        int c  = r - a * wk;
        int jj = c_PJ[p];
        md_w3j[g]  = p * 125 + a * 25 + c;
        md_nb[g]   = 2 * jj + 1;
        md_yoff[g] = (jj == 0) ? -1 : ((jj == 1) ? 0 : 3);
        md_pw[g]   = c_PW[p];
        md_pos[g]  = c_OFFP[p] + r;
    }
    #pragma unroll
    for (int q = 0; q < 4; ++q) {
        int e = 4 * wr + q;
        if (cutsm[e] == 0.f) continue;      // dead edge (warp-uniform)
        #pragma unroll
        for (int g = 0; g < 4; ++g) {
            if (!md_v[g]) continue;
            const float* wb = w3jsm + md_w3j[g];
            float a;
            if (md_yoff[g] < 0) {
                a = wb[0];
            } else {
                a = 0.f;
                for (int b = 0; b < md_nb[g]; ++b)
                    a = fmaf(wb[5 * b], ysm[e * 8 + md_yoff[g] + b], a);
            }
            Msm[e * M_PITCH + md_pos[g]] = a * md_pw[g];
        }
    }
    __syncwarp();

    // ================= Phase E: radial lookup + tensor product + scatter ===
    #pragma unroll
    for (int q = 0; q < 4; ++q) {
        int e = 4 * wr + q;
        float cutv = cutsm[e];
        if (cutv == 0.f) continue;          // warp-uniform skip
        int sn = srcsm[e], dn = dstsm[e];

        // radial weights via table lerp (d < 4 guaranteed here)
        float x = distsm[e] * ((float)RTAB_N * 0.25f);
        int i0 = (int)x;
        i0 = (i0 > RTAB_N - 1) ? (RTAB_N - 1) : i0;
        float f = x - (float)i0;
        const float* T0 = g_rtab + i0 * NRAD + u;
        float wv[NPATHS];
        #pragma unroll
        for (int p = 0; p < NPATHS; ++p) {
            float a = T0[p * 32];
            float b = T0[NRAD + p * 32];
            wv[p] = fmaf(b - a, f, a) * cutv;
        }

        const float* xb = nodes + (size_t)sn * FEAT;
        float x0r = xb[u];
        float x1r[3], x2r[5];
        #pragma unroll
        for (int a = 0; a < 3; ++a) x1r[a] = xb[32 + u * 3 + a];
        #pragma unroll
        for (int a = 0; a < 5; ++a) x2r[a] = xb[128 + u * 5 + a];

        const float4* M4 = reinterpret_cast<const float4*>(Msm + e * M_PITCH);
        float m0 = 0.f, m1[3] = {0.f, 0.f, 0.f}, m2[5] = {0.f, 0.f, 0.f, 0.f, 0.f};
        float s;

        {   // S1: floats 0..31 -> p0..p4
            float A[32];
            #pragma unroll
            for (int i = 0; i < 8; ++i)
                *reinterpret_cast<float4*>(&A[4 * i]) = M4[i];
            m0 = fmaf(wv[0], x0r * A[0], m0);
            #pragma unroll
            for (int c = 0; c < 3; ++c) m1[c] = fmaf(wv[1], x0r * A[4 + c], m1[c]);
            #pragma unroll
            for (int c = 0; c < 5; ++c) m2[c] = fmaf(wv[2], x0r * A[8 + c], m2[c]);
            #pragma unroll
            for (int c = 0; c < 3; ++c) {
                s = x1r[0] * A[16 + c] + x1r[1] * A[19 + c] + x1r[2] * A[22 + c];
                m1[c] = fmaf(wv[3], s, m1[c]);
            }
            s = x1r[0] * A[28] + x1r[1] * A[29] + x1r[2] * A[30];
            m0 = fmaf(wv[4], s, m0);
        }
        {   // S2: floats 32..59 -> p5, p6
            float A[28];
            #pragma unroll
            for (int i = 0; i < 7; ++i)
                *reinterpret_cast<float4*>(&A[4 * i]) = M4[8 + i];
            #pragma unroll
            for (int c = 0; c < 5; ++c) {
                s = x1r[0] * A[c] + x1r[1] * A[5 + c] + x1r[2] * A[10 + c];
                m2[c] = fmaf(wv[5], s, m2[c]);
            }
            #pragma unroll
            for (int c = 0; c < 3; ++c) {
                s = x1r[0] * A[16 + c] + x1r[1] * A[19 + c] + x1r[2] * A[22 + c];
                m1[c] = fmaf(wv[6], s, m1[c]);
            }
        }
        {   // S3: floats 60..87 -> p7 (2,0,2): A[a*5+c]
            float A[28];
            #pragma unroll
            for (int i = 0; i < 7; ++i)
                *reinterpret_cast<float4*>(&A[4 * i]) = M4[15 + i];
            #pragma unroll
            for (int c = 0; c < 5; ++c) {
                s = 0.f;
                #pragma unroll
                for (int a = 0; a < 5; ++a) s = fmaf(x2r[a], A[a * 5 + c], s);
                m2[c] = fmaf(wv[7], s, m2[c]);
            }
        }
        {   // S4: floats 88..111 -> p8 (A[a*3+c]), p9 (A[16+a])
            float A[24];
            #pragma unroll
            for (int i = 0; i < 6; ++i)
                *reinterpret_cast<float4*>(&A[4 * i]) = M4[22 + i];
            #pragma unroll
            for (int c = 0; c < 3; ++c) {
                s = 0.f;
                #pragma unroll
                for (int a = 0; a < 5; ++a) s = fmaf(x2r[a], A[a * 3 + c], s);
                m1[c] = fmaf(wv[8], s, m1[c]);
            }
            s = 0.f;
            #pragma unroll
            for (int a = 0; a < 5; ++a) s = fmaf(x2r[a], A[16 + a], s);
            m0 = fmaf(wv[9], s, m0);
        }
        {   // S5: floats 112..136 -> p10 (2,2,2): A[a*5+c]
            float A[28];
            #pragma unroll
            for (int i = 0; i < 7; ++i)
                *reinterpret_cast<float4*>(&A[4 * i]) = M4[28 + i];
            #pragma unroll
            for (int c = 0; c < 5; ++c) {
                s = 0.f;
                #pragma unroll
                for (int a = 0; a < 5; ++a) s = fmaf(x2r[a], A[a * 5 + c], s);
                m2[c] = fmaf(wv[10], s, m2[c]);
            }
        }

        // stage message in out-layout order, then vectorized atomic scatter
        msgw[u] = m0;
        #pragma unroll
        for (int a = 0; a < 3; ++a) msgw[32 + u * 3 + a] = m1[a];
        #pragma unroll
        for (int a = 0; a < 5; ++a) msgw[128 + u * 5 + a] = m2[a];
        __syncwarp();

        float* ob = out + (size_t)dn * FEAT;
        const float4* mg4 = reinterpret_cast<const float4*>(msgw);
        {
            float4 v0 = mg4[u];
            red4(ob + 4 * u, v0.x, v0.y, v0.z, v0.w);
            float4 v1 = mg4[u + 32];
            red4(ob + 4 * (u + 32), v1.x, v1.y, v1.z, v1.w);
            if (u < 8) {
                float4 v2 = mg4[u + 64];
                red4(ob + 4 * (u + 64), v2.x, v2.y, v2.z, v2.w);
            }
        }
        __syncwarp();
    }
}

// ---------------------------------------------------------------------------
extern "C" void kernel_launch(void* const* d_in, const int* in_sizes, int n_in,
                              void* d_out, int out_size) {
    const float* nodes = (const float*)d_in[0];
    const float* pos   = (const float*)d_in[1];
    const int*   src   = (const int*)d_in[2];
    const int*   dst   = (const int*)d_in[3];
    const float* w1    = (const float*)d_in[4];
    const float* b1    = (const float*)d_in[5];
    const float* w2    = (const float*)d_in[6];
    const float* b2    = (const float*)d_in[7];
    float* out = (float*)d_out;

    setup_kernel<<<SETUP_BLOCKS, 128>>>(out, out_size / 4);
    rtab_kernel<<<RTAB_ROWS, 128>>>(w1, b1, w2, b2);

    cudaFuncSetAttribute(conv_kernel,
                         cudaFuncAttributeMaxDynamicSharedMemorySize, SMEM_BYTES);
    int nblocks = (N_EDGES + EPB - 1) / EPB;
    conv_kernel<<<nblocks, BLK, SMEM_BYTES>>>(nodes, pos, src, dst, out);
}

// round 7
// speedup vs baseline: 2.9603x; 1.6204x over previous
#include <cuda_runtime.h>
#include <cuda_bf16.h>
#include <math.h>

// ---------------------------------------------------------------------------
// Problem constants
// ---------------------------------------------------------------------------
#define N_NODES   10000
#define N_EDGES   250000
#define FF        32
#define HIDDEN    64
#define NPATHS    11
#define FEAT      288
#define NRAD      352

#define EPB       32          // edges per block
#define BLK       256         // threads per block
#define M_PITCH   144         // padded pitch for M[e][elem]; path blocks 16B-aligned

#define RTAB_N    8192        // intervals over d in [0,4]
#define RTAB_ROWS (RTAB_N + 1)

// PATHS = [(0,0,0),(0,1,1),(0,2,2),(1,0,1),(1,1,0),(1,1,2),
//          (1,2,1),(2,0,2),(2,1,1),(2,2,0),(2,2,2)]
__constant__ int c_PI[NPATHS]  = {0,0,0,1,1,1,1,2,2,2,2};
__constant__ int c_PJ[NPATHS]  = {0,1,2,0,1,1,2,0,1,2,2};
__constant__ int c_PK[NPATHS]  = {0,1,2,1,0,2,1,2,1,0,2};
// dense element-offset of path p (sizes {1,3,5,9,3,15,9,25,15,5,25} -> 115)
__constant__ int c_OFF[NPATHS]  = {0,1,4,9,18,21,36,45,70,85,90};
// padded (16B-aligned) offsets within the 144-float per-edge M vector
__constant__ int c_OFFP[NPATHS] = {0,4,8,16,28,32,48,60,88,104,112};
// PATH_W[p]/sqrt(25)
__constant__ float c_PW[NPATHS] = {
    0.11547005383792515f, 0.17320508075688773f, 0.22360679774997896f,
    0.17320508075688773f, 0.11547005383792515f, 0.22360679774997896f,
    0.17320508075688773f, 0.22360679774997896f, 0.17320508075688773f,
    0.11547005383792515f, 0.22360679774997896f};

// Dense padded W3J: [path][a*25 + b*5 + c]
__device__ float g_w3j[NPATHS * 125];
// Interleaved radial table: g_rtab2[i*NRAD+r] = {radial_raw(d_i)[r], radial_raw(d_{i+1})[r]}
__device__ float2 g_rtab2[RTAB_N * NRAD];        // 23 MB static scratch
// Channel-major repacked node features
__device__ float g_nodesT[N_NODES * FEAT];       // 11.5 MB static scratch

// ---------------------------------------------------------------------------
// Setup kernel: zero output + compute W3J (sparse-scatter formulation).
// ---------------------------------------------------------------------------
__device__ __forceinline__ float ffact(int n) {
    float r = 1.0f;
    for (int i = 2; i <= n; ++i) r *= (float)i;
    return r;
}

__device__ float su2_cg_f(int j1, int j2, int j3, int m1, int m2, int m3) {
    if (m1 + m2 != m3) return 0.0f;
    float pref = sqrtf((2.0f * j3 + 1.0f) * ffact(j1 + j2 - j3) * ffact(j1 - j2 + j3) *
                       ffact(-j1 + j2 + j3) / ffact(j1 + j2 + j3 + 1));
    pref *= sqrtf(ffact(j3 + m3) * ffact(j3 - m3) * ffact(j1 - m1) * ffact(j1 + m1) *
                  ffact(j2 - m2) * ffact(j2 + m2));
    float s = 0.0f;
    for (int k = 0; k <= j1 + j2 - j3; ++k) {
        int e1 = j1 + j2 - j3 - k, e2 = j1 - m1 - k, e3 = j2 + m2 - k;
        int e4 = j3 - j2 + m1 + k, e5 = j3 - j1 - m2 + k;
        if (e1 < 0 || e2 < 0 || e3 < 0 || e4 < 0 || e5 < 0) continue;
        float term = 1.0f / (ffact(k) * ffact(e1) * ffact(e2) * ffact(e3) *
                             ffact(e4) * ffact(e5));
        s += (k & 1) ? -term : term;
    }
    return pref * s;
}

// nonzeros of row r of q(l), including the (-1j)^l prefactor. Returns count (1 or 2).
__device__ __forceinline__ int qrow(int l, int r, int* col, float* re, float* im) {
    const float is2 = 0.70710678118654752440f;
    int m = r - l;
    int cnt;
    float a[2], b[2];
    if (m < 0) {
        col[0] = l - m; a[0] = is2;  b[0] = 0.f;
        col[1] = l + m; a[1] = 0.f;  b[1] = -is2;
        cnt = 2;
    } else if (m == 0) {
        col[0] = l; a[0] = 1.f; b[0] = 0.f;
        cnt = 1;
    } else {
        float sg = (m & 1) ? -1.f : 1.f;
        col[0] = l + m; a[0] = sg * is2; b[0] = 0.f;
        col[1] = l - m; a[1] = 0.f;      b[1] = sg * is2;
        cnt = 2;
    }
    #pragma unroll
    for (int q = 0; q < 2; ++q) {
        if (q >= cnt) break;
        float A = a[q], B = b[q];
        if (l == 1) { float tA = B, tB = -A; A = tA; B = tB; }   // *(-i)
        else if (l == 2) { A = -A; B = -B; }                     // *(-1)
        re[q] = A; im[q] = B;
    }
    return cnt;
}

#define SETUP_BLOCKS 512

__global__ void __launch_bounds__(128) setup_kernel(float* __restrict__ out, int n4) {
    {
        float4* o4 = (float4*)out;
        float4 z = make_float4(0.f, 0.f, 0.f, 0.f);
        for (int i = blockIdx.x * blockDim.x + threadIdx.x; i < n4;
             i += gridDim.x * blockDim.x)
            o4[i] = z;
    }
    if (blockIdx.x >= NPATHS) return;

    int p = blockIdx.x, t = threadIdx.x;
    int l1 = c_PI[p], l2 = c_PJ[p], l3 = c_PK[p];
    int d1 = 2 * l1 + 1, d2 = 2 * l2 + 1, d3 = 2 * l3 + 1;
    int n = d1 * d2 * d3;
    __shared__ float C[125], Wre[125], Wim[125];
    __shared__ float sel[2];

    for (int idx = t; idx < n; idx += blockDim.x) {
        int i = idx / (d2 * d3), k = (idx / d3) % d2, m = idx % d3;
        C[idx] = su2_cg_f(l1, l2, l3, i - l1, k - l2, m - l3);
        Wre[idx] = 0.f; Wim[idx] = 0.f;
    }
    __syncthreads();

    // sparse scatter: each nonzero C entry contributes <=8 outputs
    for (int idx = t; idx < n; idx += blockDim.x) {
        float cc = C[idx];
        if (cc == 0.f) continue;
        int i = idx / (d2 * d3), k = (idx / d3) % d2, m = idx % d3;
        int   c1[2], c2[2], c3[2];
        float a1[2], b1[2], a2[2], b2[2], a3[2], b3[2];
        int n1 = qrow(l1, i, c1, a1, b1);
        int n2 = qrow(l2, k, c2, a2, b2);
        int n3 = qrow(l3, m, c3, a3, b3);
        for (int x = 0; x < n1; ++x)
            for (int y = 0; y < n2; ++y) {
                float pr = a1[x] * a2[y] - b1[x] * b2[y];
                float pi = a1[x] * b2[y] + b1[x] * a2[y];
                for (int z = 0; z < n3; ++z) {
                    float rr = pr * a3[z] + pi * b3[z];   // * conj(q3)
                    float ri = pi * a3[z] - pr * b3[z];
                    int o = (c1[x] * d2 + c2[y]) * d3 + c3[z];
                    atomicAdd(&Wre[o], cc * rr);
                    atomicAdd(&Wim[o], cc * ri);
                }
            }
    }
    __syncthreads();

    if (t == 0) {
        float nr = 0.0f, ni = 0.0f;
        for (int idx = 0; idx < n; ++idx) {
            nr += Wre[idx] * Wre[idx];
            ni += Wim[idx] * Wim[idx];
        }
        nr = sqrtf(nr); ni = sqrtf(ni);
        sel[0] = (nr >= ni) ? 1.0f : 0.0f;
        sel[1] = (nr >= ni) ? nr : ni;
    }
    __syncthreads();

    bool useRe = sel[0] > 0.5f;
    float inv = 1.0f / sel[1];
    for (int idx = t; idx < 125; idx += blockDim.x) {
        int a = idx / 25, b = (idx / 5) % 5, c = idx % 5;
        float v = 0.0f;
        if (a < d1 && b < d2 && c < d3) {
            float wv = useRe ? Wre[(a * d2 + b) * d3 + c] : Wim[(a * d2 + b) * d3 + c];
            v = wv * inv;
        }
        g_w3j[p * 125 + idx] = v;
    }
}

// ---------------------------------------------------------------------------
// Radial table build: row i = radial_raw(d_i), interleaved as {row i, row i+1}.
// ---------------------------------------------------------------------------
__global__ void __launch_bounds__(128) rtab_kernel(
    const float* __restrict__ w1, const float* __restrict__ b1,
    const float* __restrict__ w2, const float* __restrict__ b2)
{
    __shared__ float h[HIDDEN];
    int i = blockIdx.x;
    int t = threadIdx.x;
    float d = (float)i * (4.0f / (float)RTAB_N);

    if (t < HIDDEN) {
        float tt = d * 0.2f;                           // d / BESSEL_END
        float a = b1[t];
        if (tt > 0.0f && tt < 1.0f) {
            float cc = 0.6324555320336759f / tt;       // sqrt(2/5)/t
            #pragma unroll
            for (int n = 1; n <= 8; ++n) {
                float bv = cc * sinf((float)n * 3.14159265358979323846f * tt);
                a = fmaf(bv, w1[(n - 1) * HIDDEN + t], a);
            }
        }
        h[t] = a / (1.0f + __expf(-a));                // silu
    }
    __syncthreads();

    float* tab = reinterpret_cast<float*>(g_rtab2);
    for (int r = t; r < NRAD; r += 128) {
        float s = b2[r];
        #pragma unroll 8
        for (int j = 0; j < HIDDEN; ++j) s = fmaf(h[j], w2[j * NRAD + r], s);
        if (i < RTAB_N) tab[2 * (i * NRAD + r)] = s;            // .x of row i
        if (i > 0)      tab[2 * ((i - 1) * NRAD + r) + 1] = s;  // .y of row i-1
    }
}

// ---------------------------------------------------------------------------
// Node repack: channel-major layout for coalesced per-lane gathers.
//   dst[n][r]: r<32 -> x0[r]; 32..127 -> x1[(r-32)&31][(r-32)>>5];
//              128..287 -> x2[(r-128)&31][(r-128)>>5]
// ---------------------------------------------------------------------------
__global__ void __launch_bounds__(256) repack_kernel(const float* __restrict__ nodes) {
    for (int idx = blockIdx.x * 256 + threadIdx.x; idx < N_NODES * FEAT;
         idx += gridDim.x * 256) {
        int n = idx / FEAT, r = idx - n * FEAT;
        float v;
        if (r < 32) {
            v = nodes[n * FEAT + r];
        } else if (r < 128) {
            int a = (r - 32) >> 5, uu = (r - 32) & 31;
            v = nodes[n * FEAT + 32 + uu * 3 + a];
        } else {
            int a = (r - 128) >> 5, uu = (r - 128) & 31;
            v = nodes[n * FEAT + 128 + uu * 5 + a];
        }
        g_nodesT[idx] = v;
    }
}

// ---------------------------------------------------------------------------
__device__ __forceinline__ void red4(float* p, float a, float b, float c, float d) {
    asm volatile("red.global.add.v4.f32 [%0], {%1, %2, %3, %4};"
                 :: "l"(p), "f"(a), "f"(b), "f"(c), "f"(d) : "memory");
}

// dynamic smem layout (float slots); MSM and MSG are 16B-aligned
#define SM_MSM   0                        // 144*32 = 4608
#define SM_YSM   4608                     // 8*32 = 256
#define SM_MSG   4864                     // 8*296 = 2368
#define SM_W3J   (SM_MSG + 2368)          // 1375
#define SM_CUT   (SM_W3J + 1375)          // 32
#define SM_DIST  (SM_CUT + 32)            // 32
#define SM_SRC   (SM_DIST + 32)           // 32 (int)
#define SM_DST   (SM_SRC + 32)            // 32 (int)
#define SM_TOTALF (SM_DST + 32)           // 8799 floats
#define SMEM_BYTES (SM_TOTALF * 4)        // 35196 B

__global__ void __launch_bounds__(BLK, 3) conv_kernel(
    const float* __restrict__ pos,
    const int* __restrict__ src, const int* __restrict__ dst,
    float* __restrict__ out)
{
    extern __shared__ float smf[];
    float* Msm   = smf + SM_MSM;
    float* ysm   = smf + SM_YSM;
    float* w3jsm = smf + SM_W3J;
    float* cutsm = smf + SM_CUT;
    float* distsm= smf + SM_DIST;
    int*   srcsm = (int*)(smf + SM_SRC);
    int*   dstsm = (int*)(smf + SM_DST);

    const int t  = threadIdx.x;
    const int u  = t & 31;       // lane == channel
    const int wr = t >> 5;       // warp 0..7 owns edges 4*wr .. 4*wr+3
    float* msgw = smf + SM_MSG + wr * 296;

    // stage W3J table into smem (1375 floats)
    #pragma unroll
    for (int r = 0; r < 6; ++r) {
        int idx = r * BLK + t;
        if (idx < NPATHS * 125) w3jsm[idx] = g_w3j[idx];
    }

    // ================= Phase A: per-edge geometry (threads 0..31) ==========
    if (t < EPB) {
        int eg = blockIdx.x * EPB + t;
        float cut = 0.f, ux = 0.f, uy = 0.f, uz = 0.f, d = 0.f;
        int sn = 0, dn = 0;
        if (eg < N_EDGES) {
            sn = src[eg]; dn = dst[eg];
            float px = pos[3 * sn]     - pos[3 * dn];
            float py = pos[3 * sn + 1] - pos[3 * dn + 1];
            float pz = pos[3 * sn + 2] - pos[3 * dn + 2];
            d = sqrtf(px * px + py * py + pz * pz);
            float rin = 1.0f / fmaxf(d, 1e-12f);
            ux = px * rin; uy = py * rin; uz = pz * rin;
            if (d < 4.0f) {
                float uu = d * 0.25f;
                float u2 = uu * uu, u4 = u2 * u2, u5 = u4 * uu;
                cut = 1.0f - 6.0f * u5 + 5.0f * u5 * uu;
            }
        }
        cutsm[t] = cut;
        distsm[t] = d;
        srcsm[t] = sn; dstsm[t] = dn;
        const float s3 = 1.7320508075688772f, s15 = 3.872983346207417f;
        const float s5h = 1.118033988749895f, s15h = 1.9364916731037085f;
        ysm[t * 8 + 0] = s3 * uy;
        ysm[t * 8 + 1] = s3 * uz;
        ysm[t * 8 + 2] = s3 * ux;
        ysm[t * 8 + 3] = s15 * ux * uy;
        ysm[t * 8 + 4] = s15 * uy * uz;
        ysm[t * 8 + 5] = s5h * (3.0f * uz * uz - 1.0f);
        ysm[t * 8 + 6] = s15 * ux * uz;
        ysm[t * 8 + 7] = s15h * (ux * ux - uy * uy);
    }
    __syncthreads();

    // ================= Phase D: per-edge M matrices (padded layout) ========
    int   md_w3j[4], md_nb[4], md_yoff[4], md_pos[4];
    float md_pw[4];
    bool  md_v[4];
    #pragma unroll
    for (int g = 0; g < 4; ++g) {
        int idx = g * 32 + u;
        md_v[g] = (idx < 115);
        int p = 10;
        if (md_v[g]) { while (c_OFF[p] > idx) --p; } else { p = 0; }
        int r  = idx - c_OFF[p];
        int wk = 2 * c_PK[p] + 1;
        int a  = r / wk;
        int c  = r - a * wk;
        int jj = c_PJ[p];
        md_w3j[g]  = p * 125 + a * 25 + c;
        md_nb[g]   = 2 * jj + 1;
        md_yoff[g] = (jj == 0) ? -1 : ((jj == 1) ? 0 : 3);
        md_pw[g]   = c_PW[p];
        md_pos[g]  = c_OFFP[p] + r;
    }
    #pragma unroll
    for (int q = 0; q < 4; ++q) {
        int e = 4 * wr + q;
        if (cutsm[e] == 0.f) continue;      // dead edge (warp-uniform)
        #pragma unroll
        for (int g = 0; g < 4; ++g) {
            if (!md_v[g]) continue;
            const float* wb = w3jsm + md_w3j[g];
            float a;
            if (md_yoff[g] < 0) {
                a = wb[0];
            } else {
                a = 0.f;
                for (int b = 0; b < md_nb[g]; ++b)
                    a = fmaf(wb[5 * b], ysm[e * 8 + md_yoff[g] + b], a);
            }
            Msm[e * M_PITCH + md_pos[g]] = a * md_pw[g];
        }
    }
    __syncwarp();

    // ================= Phase E: radial lookup + tensor product + scatter ===
    #pragma unroll
    for (int q = 0; q < 4; ++q) {
        int e = 4 * wr + q;
        float cutv = cutsm[e];
        if (cutv == 0.f) continue;          // warp-uniform skip
        int sn = srcsm[e], dn = dstsm[e];

        // radial weights via interleaved-table lerp (d < 4 guaranteed here)
        float x = distsm[e] * ((float)RTAB_N * 0.25f);
        int i0 = (int)x;
        i0 = (i0 > RTAB_N - 1) ? (RTAB_N - 1) : i0;
        float f = x - (float)i0;
        const float2* T = g_rtab2 + i0 * NRAD + u;
        float wv[NPATHS];
        #pragma unroll
        for (int p = 0; p < NPATHS; ++p) {
            float2 ab = T[p * 32];
            wv[p] = fmaf(ab.y - ab.x, f, ab.x) * cutv;
        }

        // coalesced channel-major node gather
        const float* xb = g_nodesT + (size_t)sn * FEAT;
        float x0r = xb[u];
        float x1r[3], x2r[5];
        #pragma unroll
        for (int a = 0; a < 3; ++a) x1r[a] = xb[32 + a * 32 + u];
        #pragma unroll
        for (int a = 0; a < 5; ++a) x2r[a] = xb[128 + a * 32 + u];

        const float4* M4 = reinterpret_cast<const float4*>(Msm + e * M_PITCH);
        float m0 = 0.f, m1[3] = {0.f, 0.f, 0.f}, m2[5] = {0.f, 0.f, 0.f, 0.f, 0.f};
        float s;

        {   // S1: floats 0..31 -> p0..p4
            float A[32];
            #pragma unroll
            for (int i = 0; i < 8; ++i)
                *reinterpret_cast<float4*>(&A[4 * i]) = M4[i];
            m0 = fmaf(wv[0], x0r * A[0], m0);
            #pragma unroll
            for (int c = 0; c < 3; ++c) m1[c] = fmaf(wv[1], x0r * A[4 + c], m1[c]);
            #pragma unroll
            for (int c = 0; c < 5; ++c) m2[c] = fmaf(wv[2], x0r * A[8 + c], m2[c]);
            #pragma unroll
            for (int c = 0; c < 3; ++c) {
                s = x1r[0] * A[16 + c] + x1r[1] * A[19 + c] + x1r[2] * A[22 + c];
                m1[c] = fmaf(wv[3], s, m1[c]);
            }
            s = x1r[0] * A[28] + x1r[1] * A[29] + x1r[2] * A[30];
            m0 = fmaf(wv[4], s, m0);
        }
        {   // S2: floats 32..59 -> p5, p6
            float A[28];
            #pragma unroll
            for (int i = 0; i < 7; ++i)
                *reinterpret_cast<float4*>(&A[4 * i]) = M4[8 + i];
            #pragma unroll
            for (int c = 0; c < 5; ++c) {
                s = x1r[0] * A[c] + x1r[1] * A[5 + c] + x1r[2] * A[10 + c];
                m2[c] = fmaf(wv[5], s, m2[c]);
            }
            #pragma unroll
            for (int c = 0; c < 3; ++c) {
                s = x1r[0] * A[16 + c] + x1r[1] * A[19 + c] + x1r[2] * A[22 + c];
                m1[c] = fmaf(wv[6], s, m1[c]);
            }
        }
        {   // S3: floats 60..87 -> p7 (2,0,2): A[a*5+c]
            float A[28];
            #pragma unroll
            for (int i = 0; i < 7; ++i)
                *reinterpret_cast<float4*>(&A[4 * i]) = M4[15 + i];
            #pragma unroll
            for (int c = 0; c < 5; ++c) {
                s = 0.f;
                #pragma unroll
                for (int a = 0; a < 5; ++a) s = fmaf(x2r[a], A[a * 5 + c], s);
                m2[c] = fmaf(wv[7], s, m2[c]);
            }
        }
        {   // S4: floats 88..111 -> p8 (A[a*3+c]), p9 (A[16+a])
            float A[24];
            #pragma unroll
            for (int i = 0; i < 6; ++i)
                *reinterpret_cast<float4*>(&A[4 * i]) = M4[22 + i];
            #pragma unroll
            for (int c = 0; c < 3; ++c) {
                s = 0.f;
                #pragma unroll
                for (int a = 0; a < 5; ++a) s = fmaf(x2r[a], A[a * 3 + c], s);
                m1[c] = fmaf(wv[8], s, m1[c]);
            }
            s = 0.f;
            #pragma unroll
            for (int a = 0; a < 5; ++a) s = fmaf(x2r[a], A[16 + a], s);
            m0 = fmaf(wv[9], s, m0);
        }
        {   // S5: floats 112..136 -> p10 (2,2,2): A[a*5+c]
            float A[28];
            #pragma unroll
            for (int i = 0; i < 7; ++i)
                *reinterpret_cast<float4*>(&A[4 * i]) = M4[28 + i];
            #pragma unroll
            for (int c = 0; c < 5; ++c) {
                s = 0.f;
                #pragma unroll
                for (int a = 0; a < 5; ++a) s = fmaf(x2r[a], A[a * 5 + c], s);
                m2[c] = fmaf(wv[10], s, m2[c]);
            }
        }

        // stage message in out-layout order, then vectorized atomic scatter
        msgw[u] = m0;
        #pragma unroll
        for (int a = 0; a < 3; ++a) msgw[32 + u * 3 + a] = m1[a];
        #pragma unroll
        for (int a = 0; a < 5; ++a) msgw[128 + u * 5 + a] = m2[a];
        __syncwarp();

        float* ob = out + (size_t)dn * FEAT;
        const float4* mg4 = reinterpret_cast<const float4*>(msgw);
        {
            float4 v0 = mg4[u];
            red4(ob + 4 * u, v0.x, v0.y, v0.z, v0.w);
            float4 v1 = mg4[u + 32];
            red4(ob + 4 * (u + 32), v1.x, v1.y, v1.z, v1.w);
            if (u < 8) {
                float4 v2 = mg4[u + 64];
                red4(ob + 4 * (u + 64), v2.x, v2.y, v2.z, v2.w);
            }
        }
        __syncwarp();
    }
}

// ---------------------------------------------------------------------------
extern "C" void kernel_launch(void* const* d_in, const int* in_sizes, int n_in,
                              void* d_out, int out_size) {
    const float* nodes = (const float*)d_in[0];
    const float* pos   = (const float*)d_in[1];
    const int*   src   = (const int*)d_in[2];
    const int*   dst   = (const int*)d_in[3];
    const float* w1    = (const float*)d_in[4];
    const float* b1    = (const float*)d_in[5];
    const float* w2    = (const float*)d_in[6];
    const float* b2    = (const float*)d_in[7];
    float* out = (float*)d_out;

    setup_kernel<<<SETUP_BLOCKS, 128>>>(out, out_size / 4);
    rtab_kernel<<<RTAB_ROWS, 128>>>(w1, b1, w2, b2);
    repack_kernel<<<(N_NODES * FEAT + 255) / 256, 256>>>(nodes);

    cudaFuncSetAttribute(conv_kernel,
                         cudaFuncAttributeMaxDynamicSharedMemorySize, SMEM_BYTES);
    int nblocks = (N_EDGES + EPB - 1) / EPB;
    conv_kernel<<<nblocks, BLK, SMEM_BYTES>>>(pos, src, dst, out);
}

// round 8
// speedup vs baseline: 3.5956x; 1.2146x over previous
#include <cuda_runtime.h>
#include <cuda_bf16.h>
#include <math.h>

// ---------------------------------------------------------------------------
// Problem constants
// ---------------------------------------------------------------------------
#define N_NODES   10000
#define N_EDGES   250000
#define FF        32
#define HIDDEN    64
#define NPATHS    11
#define FEAT      288
#define NRAD      352

#define EPB       64          // edges per block
#define BLK       256         // threads per block (8 warps, 8 edges/warp)
#define M_PITCH   144         // padded pitch for M[e][elem]; path blocks 16B-aligned
#define Y_PITCH   16          // ysm pitch: 8 harmonics, [8]=1, [9..15]=0

#define RTAB_N    8192        // intervals over d in [0,4]
#define RTAB_ROWS (RTAB_N + 1)

// PATHS = [(0,0,0),(0,1,1),(0,2,2),(1,0,1),(1,1,0),(1,1,2),
//          (1,2,1),(2,0,2),(2,1,1),(2,2,0),(2,2,2)]
__constant__ int c_PI[NPATHS]  = {0,0,0,1,1,1,1,2,2,2,2};
__constant__ int c_PJ[NPATHS]  = {0,1,2,0,1,1,2,0,1,2,2};
__constant__ int c_PK[NPATHS]  = {0,1,2,1,0,2,1,2,1,0,2};
// dense element-offset of path p (sizes {1,3,5,9,3,15,9,25,15,5,25} -> 115)
__constant__ int c_OFF[NPATHS]  = {0,1,4,9,18,21,36,45,70,85,90};
// padded (16B-aligned) offsets within the 144-float per-edge M vector
__constant__ int c_OFFP[NPATHS] = {0,4,8,16,28,32,48,60,88,104,112};
// PATH_W[p]/sqrt(25)
__constant__ float c_PW[NPATHS] = {
    0.11547005383792515f, 0.17320508075688773f, 0.22360679774997896f,
    0.17320508075688773f, 0.11547005383792515f, 0.22360679774997896f,
    0.17320508075688773f, 0.22360679774997896f, 0.17320508075688773f,
    0.11547005383792515f, 0.22360679774997896f};

// Transposed, pre-scaled W3J: w3jT[idx][b] = W3J[p][a, b, c] * PW[p], rows
// padded to 5 (b >= 2j+1 -> 0), idx 115..127 all-zero.
__device__ float g_w3jT[128 * 5];
// Interleaved radial table: g_rtab2[i*NRAD+r] = {radial(d_i)[r], radial(d_{i+1})[r]}
__device__ float2 g_rtab2[RTAB_N * NRAD];        // 23 MB static scratch
// Channel-major repacked node features
__device__ float g_nodesT[N_NODES * FEAT];       // 11.5 MB static scratch

// ---------------------------------------------------------------------------
// Setup kernel: zero output + repack nodes + compute w3jT (sparse scatter).
// ---------------------------------------------------------------------------
__device__ __forceinline__ float ffact(int n) {
    float r = 1.0f;
    for (int i = 2; i <= n; ++i) r *= (float)i;
    return r;
}

__device__ float su2_cg_f(int j1, int j2, int j3, int m1, int m2, int m3) {
    if (m1 + m2 != m3) return 0.0f;
    float pref = sqrtf((2.0f * j3 + 1.0f) * ffact(j1 + j2 - j3) * ffact(j1 - j2 + j3) *
                       ffact(-j1 + j2 + j3) / ffact(j1 + j2 + j3 + 1));
    pref *= sqrtf(ffact(j3 + m3) * ffact(j3 - m3) * ffact(j1 - m1) * ffact(j1 + m1) *
                  ffact(j2 - m2) * ffact(j2 + m2));
    float s = 0.0f;
    for (int k = 0; k <= j1 + j2 - j3; ++k) {
        int e1 = j1 + j2 - j3 - k, e2 = j1 - m1 - k, e3 = j2 + m2 - k;
        int e4 = j3 - j2 + m1 + k, e5 = j3 - j1 - m2 + k;
        if (e1 < 0 || e2 < 0 || e3 < 0 || e4 < 0 || e5 < 0) continue;
        float term = 1.0f / (ffact(k) * ffact(e1) * ffact(e2) * ffact(e3) *
                             ffact(e4) * ffact(e5));
        s += (k & 1) ? -term : term;
    }
    return pref * s;
}

// nonzeros of row r of q(l), including the (-1j)^l prefactor. Returns count (1 or 2).
__device__ __forceinline__ int qrow(int l, int r, int* col, float* re, float* im) {
    const float is2 = 0.70710678118654752440f;
    int m = r - l;
    int cnt;
    float a[2], b[2];
    if (m < 0) {
        col[0] = l - m; a[0] = is2;  b[0] = 0.f;
        col[1] = l + m; a[1] = 0.f;  b[1] = -is2;
        cnt = 2;
    } else if (m == 0) {
        col[0] = l; a[0] = 1.f; b[0] = 0.f;
        cnt = 1;
    } else {
        float sg = (m & 1) ? -1.f : 1.f;
        col[0] = l + m; a[0] = sg * is2; b[0] = 0.f;
        col[1] = l - m; a[1] = 0.f;      b[1] = sg * is2;
        cnt = 2;
    }
    #pragma unroll
    for (int q = 0; q < 2; ++q) {
        if (q >= cnt) break;
        float A = a[q], B = b[q];
        if (l == 1) { float tA = B, tB = -A; A = tA; B = tB; }   // *(-i)
        else if (l == 2) { A = -A; B = -B; }                     // *(-1)
        re[q] = A; im[q] = B;
    }
    return cnt;
}

#define SETUP_BLOCKS 512

__global__ void __launch_bounds__(128) setup_kernel(
    float* __restrict__ out, int n4, const float* __restrict__ nodes)
{
    // grid-stride zero of the output (float4)
    {
        float4* o4 = (float4*)out;
        float4 z = make_float4(0.f, 0.f, 0.f, 0.f);
        for (int i = blockIdx.x * blockDim.x + threadIdx.x; i < n4;
             i += gridDim.x * blockDim.x)
            o4[i] = z;
    }
    // grid-stride node repack (channel-major)
    for (int idx = blockIdx.x * blockDim.x + threadIdx.x; idx < N_NODES * FEAT;
         idx += gridDim.x * blockDim.x) {
        int n = idx / FEAT, r = idx - n * FEAT;
        float v;
        if (r < 32) {
            v = nodes[n * FEAT + r];
        } else if (r < 128) {
            int a = (r - 32) >> 5, uu = (r - 32) & 31;
            v = nodes[n * FEAT + 32 + uu * 3 + a];
        } else {
            int a = (r - 128) >> 5, uu = (r - 128) & 31;
            v = nodes[n * FEAT + 128 + uu * 5 + a];
        }
        g_nodesT[idx] = v;
    }
    if (blockIdx.x >= NPATHS) return;

    int p = blockIdx.x, t = threadIdx.x;
    int l1 = c_PI[p], l2 = c_PJ[p], l3 = c_PK[p];
    int d1 = 2 * l1 + 1, d2 = 2 * l2 + 1, d3 = 2 * l3 + 1;
    int n = d1 * d2 * d3;
    __shared__ float C[125], Wre[125], Wim[125];
    __shared__ float sel[2];

    for (int idx = t; idx < n; idx += blockDim.x) {
        int i = idx / (d2 * d3), k = (idx / d3) % d2, m = idx % d3;
        C[idx] = su2_cg_f(l1, l2, l3, i - l1, k - l2, m - l3);
        Wre[idx] = 0.f; Wim[idx] = 0.f;
    }
    __syncthreads();

    // sparse scatter: each nonzero C entry contributes <=8 outputs
    for (int idx = t; idx < n; idx += blockDim.x) {
        float cc = C[idx];
        if (cc == 0.f) continue;
        int i = idx / (d2 * d3), k = (idx / d3) % d2, m = idx % d3;
        int   c1[2], c2[2], c3[2];
        float a1[2], b1[2], a2[2], b2[2], a3[2], b3[2];
        int n1 = qrow(l1, i, c1, a1, b1);
        int n2 = qrow(l2, k, c2, a2, b2);
        int n3 = qrow(l3, m, c3, a3, b3);
        for (int x = 0; x < n1; ++x)
            for (int y = 0; y < n2; ++y) {
                float pr = a1[x] * a2[y] - b1[x] * b2[y];
                float pi = a1[x] * b2[y] + b1[x] * a2[y];
                for (int z = 0; z < n3; ++z) {
                    float rr = pr * a3[z] + pi * b3[z];   // * conj(q3)
                    float ri = pi * a3[z] - pr * b3[z];
                    int o = (c1[x] * d2 + c2[y]) * d3 + c3[z];
                    atomicAdd(&Wre[o], cc * rr);
                    atomicAdd(&Wim[o], cc * ri);
                }
            }
    }
    __syncthreads();

    if (t == 0) {
        float nr = 0.0f, ni = 0.0f;
        for (int idx = 0; idx < n; ++idx) {
            nr += Wre[idx] * Wre[idx];
            ni += Wim[idx] * Wim[idx];
        }
        nr = sqrtf(nr); ni = sqrtf(ni);
        sel[0] = (nr >= ni) ? 1.0f : 0.0f;
        sel[1] = (nr >= ni) ? nr : ni;
    }
    __syncthreads();

    bool useRe = sel[0] > 0.5f;
    float scl = c_PW[p] / sel[1];
    const float* W = useRe ? Wre : Wim;

    // write transposed, pre-scaled rows for this path:
    //   w3jT[(off+r)*5 + b] = W[(a*d2+b)*d3 + c] * PW/norm  (b < d2, else 0)
    int off = c_OFF[p];
    int nr5 = d1 * d3 * 5;
    for (int rb = t; rb < nr5; rb += blockDim.x) {
        int r = rb / 5, b = rb - r * 5;
        int a = r / d3, c = r - a * d3;
        float v = (b < d2) ? W[(a * d2 + b) * d3 + c] * scl : 0.f;
        g_w3jT[(off + r) * 5 + b] = v;
    }
    if (p == 0)
        for (int z = t; z < 65; z += blockDim.x) g_w3jT[575 + z] = 0.f;
}

// ---------------------------------------------------------------------------
// Radial table build: 2 rows per 256-thread block; interleaved {row i, row i+1}.
// ---------------------------------------------------------------------------
__global__ void __launch_bounds__(256) rtab_kernel(
    const float* __restrict__ w1, const float* __restrict__ b1,
    const float* __restrict__ w2, const float* __restrict__ b2)
{
    __shared__ float h[2][HIDDEN];
    int t = threadIdx.x;
    int i0 = blockIdx.x * 2;
    int sub = t >> 6, l64 = t & 63;

    if (sub < 2) {
        int i = i0 + sub;
        if (i < RTAB_ROWS) {
            float d = (float)i * (4.0f / (float)RTAB_N);
            float tt = d * 0.2f;                       // d / BESSEL_END
            float a = b1[l64];
            if (tt > 0.0f && tt < 1.0f) {
                float cc = 0.6324555320336759f / tt;   // sqrt(2/5)/t
                #pragma unroll
                for (int n = 1; n <= 8; ++n) {
                    float bv = cc * sinf((float)n * 3.14159265358979323846f * tt);
                    a = fmaf(bv, w1[(n - 1) * HIDDEN + l64], a);
                }
            }
            h[sub][l64] = a / (1.0f + __expf(-a));     // silu
        }
    }
    __syncthreads();

    float* tab = reinterpret_cast<float*>(g_rtab2);
    #pragma unroll
    for (int k = 0; k < 3; ++k) {
        int o = k * 256 + t;
        if (o < 704) {
            int row = (o >= NRAD) ? 1 : 0;
            int r = o - row * NRAD;
            int i = i0 + row;
            if (i < RTAB_ROWS) {
                float s = b2[r];
                #pragma unroll 8
                for (int j = 0; j < HIDDEN; ++j) s = fmaf(h[row][j], w2[j * NRAD + r], s);
                if (i < RTAB_N) tab[2 * (i * NRAD + r)] = s;            // .x of row i
                if (i > 0)      tab[2 * ((i - 1) * NRAD + r) + 1] = s;  // .y of row i-1
            }
        }
    }
}

// ---------------------------------------------------------------------------
__device__ __forceinline__ void red4(float* p, float a, float b, float c, float d) {
    asm volatile("red.global.add.v4.f32 [%0], {%1, %2, %3, %4};"
                 :: "l"(p), "f"(a), "f"(b), "f"(c), "f"(d) : "memory");
}

// dynamic smem layout (float slots); MSM and MSG are 16B-aligned
#define SM_MSM   0                        // 144*64 = 9216
#define SM_YSM   9216                     // 16*64 = 1024
#define SM_MSG   10240                    // 8*296 = 2368
#define SM_W3JT  (SM_MSG + 2368)          // 640
#define SM_CUT   (SM_W3JT + 640)          // 64
#define SM_DIST  (SM_CUT + 64)            // 64
#define SM_SRC   (SM_DIST + 64)           // 64 (int)
#define SM_DST   (SM_SRC + 64)            // 64 (int)
#define SM_TOTALF (SM_DST + 64)           // 13504 floats
#define SMEM_BYTES (SM_TOTALF * 4)        // 54016 B

__global__ void __launch_bounds__(BLK, 3) conv_kernel(
    const float* __restrict__ pos,
    const int* __restrict__ src, const int* __restrict__ dst,
    float* __restrict__ out)
{
    extern __shared__ float smf[];
    float* Msm   = smf + SM_MSM;
    float* ysm   = smf + SM_YSM;
    float* w3jTs = smf + SM_W3JT;
    float* cutsm = smf + SM_CUT;
    float* distsm= smf + SM_DIST;
    int*   srcsm = (int*)(smf + SM_SRC);
    int*   dstsm = (int*)(smf + SM_DST);

    const int t  = threadIdx.x;
    const int u  = t & 31;       // lane == channel
    const int wr = t >> 5;       // warp 0..7 owns edges 8*wr .. 8*wr+7
    float* msgw = smf + SM_MSG + wr * 296;

    // stage w3jT table into smem (640 floats)
    #pragma unroll
    for (int r = 0; r < 3; ++r) {
        int idx = r * BLK + t;
        if (idx < 640) w3jTs[idx] = g_w3jT[idx];
    }

    // ================= Phase A: per-edge geometry (threads 0..63) ==========
    if (t < EPB) {
        int eg = blockIdx.x * EPB + t;
        float cut = 0.f, ux = 0.f, uy = 0.f, uz = 0.f, d = 0.f;
        int sn = 0, dn = 0;
        if (eg < N_EDGES) {
            sn = src[eg]; dn = dst[eg];
            float px = pos[3 * sn]     - pos[3 * dn];
            float py = pos[3 * sn + 1] - pos[3 * dn + 1];
            float pz = pos[3 * sn + 2] - pos[3 * dn + 2];
            d = sqrtf(px * px + py * py + pz * pz);
            float rin = 1.0f / fmaxf(d, 1e-12f);
            ux = px * rin; uy = py * rin; uz = pz * rin;
            if (d < 4.0f) {
                float uu = d * 0.25f;
                float u2 = uu * uu, u4 = u2 * u2, u5 = u4 * uu;
                cut = 1.0f - 6.0f * u5 + 5.0f * u5 * uu;
            }
        }
        cutsm[t] = cut;
        distsm[t] = d;
        srcsm[t] = sn; dstsm[t] = dn;
        const float s3 = 1.7320508075688772f, s15 = 3.872983346207417f;
        const float s5h = 1.118033988749895f, s15h = 1.9364916731037085f;
        float* ye = ysm + t * Y_PITCH;
        ye[0] = s3 * uy;
        ye[1] = s3 * uz;
        ye[2] = s3 * ux;
        ye[3] = s15 * ux * uy;
        ye[4] = s15 * uy * uz;
        ye[5] = s5h * (3.0f * uz * uz - 1.0f);
        ye[6] = s15 * ux * uz;
        ye[7] = s15h * (ux * ux - uy * uy);
        ye[8] = 1.0f;                    // constant slot for j=0 paths
        #pragma unroll
        for (int z = 9; z < Y_PITCH; ++z) ye[z] = 0.f;
    }
    __syncthreads();

    // ================= Phase D: per-edge M matrices ========================
    // lane-element metadata: element idx = g*32+u
    int   md_yoff[4], md_pos[4], md_row[4];
    #pragma unroll
    for (int g = 0; g < 4; ++g) {
        int idx = g * 32 + u;
        bool v = (idx < 115);
        int p = 10;
        if (v) { while (c_OFF[p] > idx) --p; } else { p = 0; }
        int r  = idx - c_OFF[p];
        int wk = 2 * c_PK[p] + 1;
        int a  = r / wk;
        int c  = r - a * wk;
        int jj = c_PJ[p];
        md_yoff[g] = (jj == 0) ? 8 : ((jj == 1) ? 0 : 3);
        md_pos[g]  = v ? (c_OFFP[p] + r) : 143;       // invalid -> pad slot
        md_row[g]  = idx * 5;                         // idx<128 rows exist (zeros >=115)
    }
    #pragma unroll
    for (int q = 0; q < 8; ++q) {
        int e = 8 * wr + q;
        if (cutsm[e] == 0.f) continue;      // dead edge (warp-uniform)
        const float* ye = ysm + e * Y_PITCH;
        #pragma unroll
        for (int g = 0; g < 4; ++g) {
            const float* wrow = w3jTs + md_row[g];
            const float* yb = ye + md_yoff[g];
            float a = wrow[0] * yb[0];
            #pragma unroll
            for (int b = 1; b < 5; ++b) a = fmaf(wrow[b], yb[b], a);
            Msm[e * M_PITCH + md_pos[g]] = a;
        }
    }
    __syncwarp();

    // ================= Phase E: radial lookup + tensor product + scatter ===
    #pragma unroll
    for (int q = 0; q < 8; ++q) {
        int e = 8 * wr + q;
        float cutv = cutsm[e];
        if (cutv == 0.f) continue;          // warp-uniform skip
        int sn = srcsm[e], dn = dstsm[e];

        // radial weights via interleaved-table lerp (d < 4 guaranteed here)
        float x = distsm[e] * ((float)RTAB_N * 0.25f);
        int i0 = (int)x;
        i0 = (i0 > RTAB_N - 1) ? (RTAB_N - 1) : i0;
        float f = x - (float)i0;
        const float2* T = g_rtab2 + i0 * NRAD + u;
        float wv[NPATHS];
        #pragma unroll
        for (int p = 0; p < NPATHS; ++p) {
            float2 ab = T[p * 32];
            wv[p] = fmaf(ab.y - ab.x, f, ab.x) * cutv;
        }

        // coalesced channel-major node gather
        const float* xb = g_nodesT + (size_t)sn * FEAT;
        float x0r = xb[u];
        float x1r[3], x2r[5];
        #pragma unroll
        for (int a = 0; a < 3; ++a) x1r[a] = xb[32 + a * 32 + u];
        #pragma unroll
        for (int a = 0; a < 5; ++a) x2r[a] = xb[128 + a * 32 + u];

        const float4* M4 = reinterpret_cast<const float4*>(Msm + e * M_PITCH);
        float m0 = 0.f, m1[3] = {0.f, 0.f, 0.f}, m2[5] = {0.f, 0.f, 0.f, 0.f, 0.f};
        float s;

        {   // S1: floats 0..31 -> p0..p4
            float A[32];
            #pragma unroll
            for (int i = 0; i < 8; ++i)
                *reinterpret_cast<float4*>(&A[4 * i]) = M4[i];
            m0 = fmaf(wv[0], x0r * A[0], m0);
            #pragma unroll
            for (int c = 0; c < 3; ++c) m1[c] = fmaf(wv[1], x0r * A[4 + c], m1[c]);
            #pragma unroll
            for (int c = 0; c < 5; ++c) m2[c] = fmaf(wv[2], x0r * A[8 + c], m2[c]);
            #pragma unroll
            for (int c = 0; c < 3; ++c) {
                s = x1r[0] * A[16 + c] + x1r[1] * A[19 + c] + x1r[2] * A[22 + c];
                m1[c] = fmaf(wv[3], s, m1[c]);
            }
            s = x1r[0] * A[28] + x1r[1] * A[29] + x1r[2] * A[30];
            m0 = fmaf(wv[4], s, m0);
        }
        {   // S2: floats 32..59 -> p5, p6
            float A[28];
            #pragma unroll
            for (int i = 0; i < 7; ++i)
                *reinterpret_cast<float4*>(&A[4 * i]) = M4[8 + i];
            #pragma unroll
            for (int c = 0; c < 5; ++c) {
                s = x1r[0] * A[c] + x1r[1] * A[5 + c] + x1r[2] * A[10 + c];
                m2[c] = fmaf(wv[5], s, m2[c]);
            }
            #pragma unroll
            for (int c = 0; c < 3; ++c) {
                s = x1r[0] * A[16 + c] + x1r[1] * A[19 + c] + x1r[2] * A[22 + c];
                m1[c] = fmaf(wv[6], s, m1[c]);
            }
        }
        {   // S3: floats 60..87 -> p7 (2,0,2): A[a*5+c]
            float A[28];
            #pragma unroll
            for (int i = 0; i < 7; ++i)
                *reinterpret_cast<float4*>(&A[4 * i]) = M4[15 + i];
            #pragma unroll
            for (int c = 0; c < 5; ++c) {
                s = 0.f;
                #pragma unroll
                for (int a = 0; a < 5; ++a) s = fmaf(x2r[a], A[a * 5 + c], s);
                m2[c] = fmaf(wv[7], s, m2[c]);
            }
        }
        {   // S4: floats 88..111 -> p8 (A[a*3+c]), p9 (A[16+a])
            float A[24];
            #pragma unroll
            for (int i = 0; i < 6; ++i)
                *reinterpret_cast<float4*>(&A[4 * i]) = M4[22 + i];
            #pragma unroll
            for (int c = 0; c < 3; ++c) {
                s = 0.f;
                #pragma unroll
                for (int a = 0; a < 5; ++a) s = fmaf(x2r[a], A[a * 3 + c], s);
                m1[c] = fmaf(wv[8], s, m1[c]);
            }
            s = 0.f;
            #pragma unroll
            for (int a = 0; a < 5; ++a) s = fmaf(x2r[a], A[16 + a], s);
            m0 = fmaf(wv[9], s, m0);
        }
        {   // S5: floats 112..136 -> p10 (2,2,2): A[a*5+c]
            float A[28];
            #pragma unroll
            for (int i = 0; i < 7; ++i)
                *reinterpret_cast<float4*>(&A[4 * i]) = M4[28 + i];
            #pragma unroll
            for (int c = 0; c < 5; ++c) {
                s = 0.f;
                #pragma unroll
                for (int a = 0; a < 5; ++a) s = fmaf(x2r[a], A[a * 5 + c], s);
                m2[c] = fmaf(wv[10], s, m2[c]);
            }
        }

        // stage message in out-layout order, then vectorized atomic scatter
        msgw[u] = m0;
        #pragma unroll
        for (int a = 0; a < 3; ++a) msgw[32 + u * 3 + a] = m1[a];
        #pragma unroll
        for (int a = 0; a < 5; ++a) msgw[128 + u * 5 + a] = m2[a];
        __syncwarp();

        float* ob = out + (size_t)dn * FEAT;
        const float4* mg4 = reinterpret_cast<const float4*>(msgw);
        {
            float4 v0 = mg4[u];
            red4(ob + 4 * u, v0.x, v0.y, v0.z, v0.w);
            float4 v1 = mg4[u + 32];
            red4(ob + 4 * (u + 32), v1.x, v1.y, v1.z, v1.w);
            if (u < 8) {
                float4 v2 = mg4[u + 64];
                red4(ob + 4 * (u + 64), v2.x, v2.y, v2.z, v2.w);
            }
        }
        __syncwarp();
    }
}

// ---------------------------------------------------------------------------
extern "C" void kernel_launch(void* const* d_in, const int* in_sizes, int n_in,
                              void* d_out, int out_size) {
    const float* nodes = (const float*)d_in[0];
    const float* pos   = (const float*)d_in[1];
    const int*   src   = (const int*)d_in[2];
    const int*   dst   = (const int*)d_in[3];
    const float* w1    = (const float*)d_in[4];
    const float* b1    = (const float*)d_in[5];
    const float* w2    = (const float*)d_in[6];
    const float* b2    = (const float*)d_in[7];
    float* out = (float*)d_out;

    setup_kernel<<<SETUP_BLOCKS, 128>>>(out, out_size / 4, nodes);
    rtab_kernel<<<(RTAB_ROWS + 1) / 2, 256>>>(w1, b1, w2, b2);

    cudaFuncSetAttribute(conv_kernel,
                         cudaFuncAttributeMaxDynamicSharedMemorySize, SMEM_BYTES);
    int nblocks = (N_EDGES + EPB - 1) / EPB;
    conv_kernel<<<nblocks, BLK, SMEM_BYTES>>>(pos, src, dst, out);
}

// round 9
// speedup vs baseline: 3.8424x; 1.0687x over previous
#include <cuda_runtime.h>
#include <cuda_bf16.h>
#include <math.h>

// ---------------------------------------------------------------------------
// Problem constants
// ---------------------------------------------------------------------------
#define N_NODES   10000
#define N_EDGES   250000
#define FF        32
#define HIDDEN    64
#define NPATHS    11
#define FEAT      288
#define NRAD      352

#define EPB       64          // edges per block
#define BLK       256         // threads per block (8 warps, 8 edges/warp)
#define M_PITCH   144         // padded pitch for M[e][elem]; path blocks 16B-aligned
#define Y_PITCH   16          // ysm pitch: 8 harmonics, [8]=1, [9..15]=0

#define RTAB_N    8192        // intervals over d in [0,4]
#define RTAB_ROWS (RTAB_N + 1)

// PATHS = [(0,0,0),(0,1,1),(0,2,2),(1,0,1),(1,1,0),(1,1,2),
//          (1,2,1),(2,0,2),(2,1,1),(2,2,0),(2,2,2)]
__constant__ int c_PI[NPATHS]  = {0,0,0,1,1,1,1,2,2,2,2};
__constant__ int c_PJ[NPATHS]  = {0,1,2,0,1,1,2,0,1,2,2};
__constant__ int c_PK[NPATHS]  = {0,1,2,1,0,2,1,2,1,0,2};
// dense element-offset of path p (sizes {1,3,5,9,3,15,9,25,15,5,25} -> 115)
__constant__ int c_OFF[NPATHS]  = {0,1,4,9,18,21,36,45,70,85,90};
// padded (16B-aligned) offsets within the 144-float per-edge M vector
__constant__ int c_OFFP[NPATHS] = {0,4,8,16,28,32,48,60,88,104,112};
// PATH_W[p]/sqrt(25)
__constant__ float c_PW[NPATHS] = {
    0.11547005383792515f, 0.17320508075688773f, 0.22360679774997896f,
    0.17320508075688773f, 0.11547005383792515f, 0.22360679774997896f,
    0.17320508075688773f, 0.22360679774997896f, 0.17320508075688773f,
    0.11547005383792515f, 0.22360679774997896f};

// Transposed, pre-scaled W3J: w3jT[idx][b] = W3J[p][a, b, c] * PW[p], rows
// padded to 5 (b >= 2j+1 -> 0), idx 115..127 all-zero.
__device__ float g_w3jT[128 * 5];
// Interleaved radial*cutoff table: g_rtab2[i*NRAD+r] = {rad(d_i)[r], rad(d_{i+1})[r]}
__device__ float2 g_rtab2[RTAB_N * NRAD];        // 23 MB static scratch
// Channel-major repacked node features
__device__ float g_nodesT[N_NODES * FEAT];       // 11.5 MB static scratch
// Channel-major output accumulator (transposed back at the end)
__device__ __align__(16) float g_outT[N_NODES * FEAT];

// ---------------------------------------------------------------------------
// Setup kernel: zero g_outT + repack nodes + compute w3jT (sparse scatter).
// ---------------------------------------------------------------------------
__device__ __forceinline__ float ffact(int n) {
    float r = 1.0f;
    for (int i = 2; i <= n; ++i) r *= (float)i;
    return r;
}

__device__ float su2_cg_f(int j1, int j2, int j3, int m1, int m2, int m3) {
    if (m1 + m2 != m3) return 0.0f;
    float pref = sqrtf((2.0f * j3 + 1.0f) * ffact(j1 + j2 - j3) * ffact(j1 - j2 + j3) *
                       ffact(-j1 + j2 + j3) / ffact(j1 + j2 + j3 + 1));
    pref *= sqrtf(ffact(j3 + m3) * ffact(j3 - m3) * ffact(j1 - m1) * ffact(j1 + m1) *
                  ffact(j2 - m2) * ffact(j2 + m2));
    float s = 0.0f;
    for (int k = 0; k <= j1 + j2 - j3; ++k) {
        int e1 = j1 + j2 - j3 - k, e2 = j1 - m1 - k, e3 = j2 + m2 - k;
        int e4 = j3 - j2 + m1 + k, e5 = j3 - j1 - m2 + k;
        if (e1 < 0 || e2 < 0 || e3 < 0 || e4 < 0 || e5 < 0) continue;
        float term = 1.0f / (ffact(k) * ffact(e1) * ffact(e2) * ffact(e3) *
                             ffact(e4) * ffact(e5));
        s += (k & 1) ? -term : term;
    }
    return pref * s;
}

// nonzeros of row r of q(l), including the (-1j)^l prefactor. Returns count (1 or 2).
__device__ __forceinline__ int qrow(int l, int r, int* col, float* re, float* im) {
    const float is2 = 0.70710678118654752440f;
    int m = r - l;
    int cnt;
    float a[2], b[2];
    if (m < 0) {
        col[0] = l - m; a[0] = is2;  b[0] = 0.f;
        col[1] = l + m; a[1] = 0.f;  b[1] = -is2;
        cnt = 2;
    } else if (m == 0) {
        col[0] = l; a[0] = 1.f; b[0] = 0.f;
        cnt = 1;
    } else {
        float sg = (m & 1) ? -1.f : 1.f;
        col[0] = l + m; a[0] = sg * is2; b[0] = 0.f;
        col[1] = l - m; a[1] = 0.f;      b[1] = sg * is2;
        cnt = 2;
    }
    #pragma unroll
    for (int q = 0; q < 2; ++q) {
        if (q >= cnt) break;
        float A = a[q], B = b[q];
        if (l == 1) { float tA = B, tB = -A; A = tA; B = tB; }   // *(-i)
        else if (l == 2) { A = -A; B = -B; }                     // *(-1)
        re[q] = A; im[q] = B;
    }
    return cnt;
}

#define SETUP_BLOCKS 2048

__global__ void __launch_bounds__(128) setup_kernel(const float* __restrict__ nodes)
{
    // grid-stride zero of the transposed accumulator (float4)
    {
        float4* o4 = (float4*)g_outT;
        float4 z = make_float4(0.f, 0.f, 0.f, 0.f);
        for (int i = blockIdx.x * blockDim.x + threadIdx.x; i < N_NODES * FEAT / 4;
             i += gridDim.x * blockDim.x)
            o4[i] = z;
    }
    // grid-stride node repack (channel-major)
    for (int idx = blockIdx.x * blockDim.x + threadIdx.x; idx < N_NODES * FEAT;
         idx += gridDim.x * blockDim.x) {
        int n = idx / FEAT, r = idx - n * FEAT;
        float v;
        if (r < 32) {
            v = nodes[n * FEAT + r];
        } else if (r < 128) {
            int a = (r - 32) >> 5, uu = (r - 32) & 31;
            v = nodes[n * FEAT + 32 + uu * 3 + a];
        } else {
            int a = (r - 128) >> 5, uu = (r - 128) & 31;
            v = nodes[n * FEAT + 128 + uu * 5 + a];
        }
        g_nodesT[idx] = v;
    }
    if (blockIdx.x >= NPATHS) return;

    int p = blockIdx.x, t = threadIdx.x;
    int l1 = c_PI[p], l2 = c_PJ[p], l3 = c_PK[p];
    int d1 = 2 * l1 + 1, d2 = 2 * l2 + 1, d3 = 2 * l3 + 1;
    int n = d1 * d2 * d3;
    __shared__ float C[125], Wre[125], Wim[125];
    __shared__ float sel[2];

    for (int idx = t; idx < n; idx += blockDim.x) {
        int i = idx / (d2 * d3), k = (idx / d3) % d2, m = idx % d3;
        C[idx] = su2_cg_f(l1, l2, l3, i - l1, k - l2, m - l3);
        Wre[idx] = 0.f; Wim[idx] = 0.f;
    }
    __syncthreads();

    // sparse scatter: each nonzero C entry contributes <=8 outputs
    for (int idx = t; idx < n; idx += blockDim.x) {
        float cc = C[idx];
        if (cc == 0.f) continue;
        int i = idx / (d2 * d3), k = (idx / d3) % d2, m = idx % d3;
        int   c1[2], c2[2], c3[2];
        float a1[2], b1[2], a2[2], b2[2], a3[2], b3[2];
        int n1 = qrow(l1, i, c1, a1, b1);
        int n2 = qrow(l2, k, c2, a2, b2);
        int n3 = qrow(l3, m, c3, a3, b3);
        for (int x = 0; x < n1; ++x)
            for (int y = 0; y < n2; ++y) {
                float pr = a1[x] * a2[y] - b1[x] * b2[y];
                float pi = a1[x] * b2[y] + b1[x] * a2[y];
                for (int z = 0; z < n3; ++z) {
                    float rr = pr * a3[z] + pi * b3[z];   // * conj(q3)
                    float ri = pi * a3[z] - pr * b3[z];
                    int o = (c1[x] * d2 + c2[y]) * d3 + c3[z];
                    atomicAdd(&Wre[o], cc * rr);
                    atomicAdd(&Wim[o], cc * ri);
                }
            }
    }
    __syncthreads();

    if (t == 0) {
        float nr = 0.0f, ni = 0.0f;
        for (int idx = 0; idx < n; ++idx) {
            nr += Wre[idx] * Wre[idx];
            ni += Wim[idx] * Wim[idx];
        }
        nr = sqrtf(nr); ni = sqrtf(ni);
        sel[0] = (nr >= ni) ? 1.0f : 0.0f;
        sel[1] = (nr >= ni) ? nr : ni;
    }
    __syncthreads();

    bool useRe = sel[0] > 0.5f;
    float scl = c_PW[p] / sel[1];
    const float* W = useRe ? Wre : Wim;

    // write transposed, pre-scaled rows for this path:
    //   w3jT[(off+r)*5 + b] = W[(a*d2+b)*d3 + c] * PW/norm  (b < d2, else 0)
    int off = c_OFF[p];
    int nr5 = d1 * d3 * 5;
    for (int rb = t; rb < nr5; rb += blockDim.x) {
        int r = rb / 5, b = rb - r * 5;
        int a = r / d3, c = r - a * d3;
        float v = (b < d2) ? W[(a * d2 + b) * d3 + c] * scl : 0.f;
        g_w3jT[(off + r) * 5 + b] = v;
    }
    if (p == 0)
        for (int z = t; z < 65; z += blockDim.x) g_w3jT[575 + z] = 0.f;
}

// ---------------------------------------------------------------------------
// Radial table build: 2 rows per 256-thread block; interleaved {row i, row i+1}.
// Table stores radial_raw(d) * poly_cutoff(d)  (both smooth in d).
// ---------------------------------------------------------------------------
__global__ void __launch_bounds__(256) rtab_kernel(
    const float* __restrict__ w1, const float* __restrict__ b1,
    const float* __restrict__ w2, const float* __restrict__ b2)
{
    __shared__ float h[2][HIDDEN];
    __shared__ float cutf[2];
    int t = threadIdx.x;
    int i0 = blockIdx.x * 2;
    int sub = t >> 6, l64 = t & 63;

    if (sub < 2) {
        int i = i0 + sub;
        if (i < RTAB_ROWS) {
            float d = (float)i * (4.0f / (float)RTAB_N);
            float tt = d * 0.2f;                       // d / BESSEL_END
            float a = b1[l64];
            if (tt > 0.0f && tt < 1.0f) {
                float cc = 0.6324555320336759f / tt;   // sqrt(2/5)/t
                #pragma unroll
                for (int n = 1; n <= 8; ++n) {
                    float bv = cc * sinf((float)n * 3.14159265358979323846f * tt);
                    a = fmaf(bv, w1[(n - 1) * HIDDEN + l64], a);
                }
            }
            h[sub][l64] = a / (1.0f + __expf(-a));     // silu
            if (l64 == 0) {
                float cv = 0.f;
                if (d < 4.0f) {
                    float uu = d * 0.25f;
                    float u2 = uu * uu, u4 = u2 * u2, u5 = u4 * uu;
                    cv = 1.0f - 6.0f * u5 + 5.0f * u5 * uu;
                }
                cutf[sub] = cv;
            }
        }
    }
    __syncthreads();

    float* tab = reinterpret_cast<float*>(g_rtab2);
    #pragma unroll
    for (int k = 0; k < 3; ++k) {
        int o = k * 256 + t;
        if (o < 704) {
            int row = (o >= NRAD) ? 1 : 0;
            int r = o - row * NRAD;
            int i = i0 + row;
            if (i < RTAB_ROWS) {
                float s = b2[r];
                #pragma unroll 8
                for (int j = 0; j < HIDDEN; ++j) s = fmaf(h[row][j], w2[j * NRAD + r], s);
                s *= cutf[row];
                if (i < RTAB_N) tab[2 * (i * NRAD + r)] = s;            // .x of row i
                if (i > 0)      tab[2 * ((i - 1) * NRAD + r) + 1] = s;  // .y of row i-1
            }
        }
    }
}

// ---------------------------------------------------------------------------
// Final transpose: out (reference layout) <- g_outT (channel-major)
// ---------------------------------------------------------------------------
__global__ void __launch_bounds__(256) untranspose_kernel(float* __restrict__ out) {
    for (int idx = blockIdx.x * 256 + threadIdx.x; idx < N_NODES * FEAT;
         idx += gridDim.x * 256) {
        int n = idx / FEAT, r = idx - n * FEAT;
        int rT;
        if (r < 32) {
            rT = r;
        } else if (r < 128) {
            int rr = r - 32;
            int uu = rr / 3, a = rr - uu * 3;
            rT = 32 + a * 32 + uu;
        } else {
            int rr = r - 128;
            int uu = rr / 5, a = rr - uu * 5;
            rT = 128 + a * 32 + uu;
        }
        out[idx] = g_outT[n * FEAT + rT];
    }
}

// ---------------------------------------------------------------------------
__device__ __forceinline__ void red1(float* p, float v) {
    asm volatile("red.global.add.f32 [%0], %1;" :: "l"(p), "f"(v) : "memory");
}

// dynamic smem layout (float slots); MSM is 16B-aligned
#define SM_MSM   0                        // 144*64 = 9216
#define SM_YSM   9216                     // 16*64 = 1024
#define SM_W3JT  10240                    // 640
#define SM_CUT   (SM_W3JT + 640)          // 64
#define SM_DIST  (SM_CUT + 64)            // 64
#define SM_SRC   (SM_DIST + 64)           // 64 (int)
#define SM_DST   (SM_SRC + 64)            // 64 (int)
#define SM_TOTALF (SM_DST + 64)           // 11136 floats
#define SMEM_BYTES (SM_TOTALF * 4)        // 44544 B

__global__ void __launch_bounds__(BLK, 3) conv_kernel(
    const float* __restrict__ pos,
    const int* __restrict__ src, const int* __restrict__ dst)
{
    extern __shared__ float smf[];
    float* Msm   = smf + SM_MSM;
    float* ysm   = smf + SM_YSM;
    float* w3jTs = smf + SM_W3JT;
    float* cutsm = smf + SM_CUT;
    float* distsm= smf + SM_DIST;
    int*   srcsm = (int*)(smf + SM_SRC);
    int*   dstsm = (int*)(smf + SM_DST);

    const int t  = threadIdx.x;
    const int u  = t & 31;       // lane == channel
    const int wr = t >> 5;       // warp 0..7 owns edges 8*wr .. 8*wr+7

    // stage w3jT table into smem (640 floats)
    #pragma unroll
    for (int r = 0; r < 3; ++r) {
        int idx = r * BLK + t;
        if (idx < 640) w3jTs[idx] = g_w3jT[idx];
    }

    // ================= Phase A: per-edge geometry (threads 0..63) ==========
    if (t < EPB) {
        int eg = blockIdx.x * EPB + t;
        float cut = 0.f, ux = 0.f, uy = 0.f, uz = 0.f, d = 0.f;
        int sn = 0, dn = 0;
        if (eg < N_EDGES) {
            sn = src[eg]; dn = dst[eg];
            float px = pos[3 * sn]     - pos[3 * dn];
            float py = pos[3 * sn + 1] - pos[3 * dn + 1];
            float pz = pos[3 * sn + 2] - pos[3 * dn + 2];
            d = sqrtf(px * px + py * py + pz * pz);
            float rin = 1.0f / fmaxf(d, 1e-12f);
            ux = px * rin; uy = py * rin; uz = pz * rin;
            if (d < 4.0f) cut = 1.0f;            // live-edge flag
        }
        cutsm[t] = cut;
        distsm[t] = d;
        srcsm[t] = sn; dstsm[t] = dn;
        const float s3 = 1.7320508075688772f, s15 = 3.872983346207417f;
        const float s5h = 1.118033988749895f, s15h = 1.9364916731037085f;
        float* ye = ysm + t * Y_PITCH;
        ye[0] = s3 * uy;
        ye[1] = s3 * uz;
        ye[2] = s3 * ux;
        ye[3] = s15 * ux * uy;
        ye[4] = s15 * uy * uz;
        ye[5] = s5h * (3.0f * uz * uz - 1.0f);
        ye[6] = s15 * ux * uz;
        ye[7] = s15h * (ux * ux - uy * uy);
        ye[8] = 1.0f;                    // constant slot for j=0 paths
        #pragma unroll
        for (int z = 9; z < Y_PITCH; ++z) ye[z] = 0.f;
    }
    __syncthreads();

    // ================= Phase D: per-edge M matrices ========================
    int   md_yoff[4], md_pos[4], md_row[4];
    #pragma unroll
    for (int g = 0; g < 4; ++g) {
        int idx = g * 32 + u;
        bool v = (idx < 115);
        int p = 10;
        if (v) { while (c_OFF[p] > idx) --p; } else { p = 0; }
        int r  = idx - c_OFF[p];
        int wk = 2 * c_PK[p] + 1;
        int a  = r / wk;
        int c  = r - a * wk;
        int jj = c_PJ[p];
        md_yoff[g] = (jj == 0) ? 8 : ((jj == 1) ? 0 : 3);
        md_pos[g]  = v ? (c_OFFP[p] + r) : 143;       // invalid -> pad slot
        md_row[g]  = idx * 5;
    }
    #pragma unroll
    for (int q = 0; q < 8; ++q) {
        int e = 8 * wr + q;
        if (cutsm[e] == 0.f) continue;      // dead edge (warp-uniform)
        const float* ye = ysm + e * Y_PITCH;
        #pragma unroll
        for (int g = 0; g < 4; ++g) {
            const float* wrow = w3jTs + md_row[g];
            const float* yb = ye + md_yoff[g];
            float a = wrow[0] * yb[0];
            #pragma unroll
            for (int b = 1; b < 5; ++b) a = fmaf(wrow[b], yb[b], a);
            Msm[e * M_PITCH + md_pos[g]] = a;
        }
    }
    __syncwarp();

    // ================= Phase E: radial lookup + tensor product + scatter ===
    #pragma unroll
    for (int q = 0; q < 8; ++q) {
        int e = 8 * wr + q;
        if (cutsm[e] == 0.f) continue;      // warp-uniform skip
        int sn = srcsm[e], dn = dstsm[e];

        // radial*cutoff via interleaved-table lerp (d < 4 guaranteed here)
        float x = distsm[e] * ((float)RTAB_N * 0.25f);
        int i0 = (int)x;
        i0 = (i0 > RTAB_N - 1) ? (RTAB_N - 1) : i0;
        float f = x - (float)i0;
        const float2* T = g_rtab2 + i0 * NRAD + u;
        float wv[NPATHS];
        #pragma unroll
        for (int p = 0; p < NPATHS; ++p) {
            float2 ab = T[p * 32];
            wv[p] = fmaf(ab.y - ab.x, f, ab.x);
        }

        // coalesced channel-major node gather
        const float* xb = g_nodesT + (size_t)sn * FEAT;
        float x0r = xb[u];
        float x1r[3], x2r[5];
        #pragma unroll
        for (int a = 0; a < 3; ++a) x1r[a] = xb[32 + a * 32 + u];
        #pragma unroll
        for (int a = 0; a < 5; ++a) x2r[a] = xb[128 + a * 32 + u];

        const float4* M4 = reinterpret_cast<const float4*>(Msm + e * M_PITCH);
        float m0 = 0.f, m1[3] = {0.f, 0.f, 0.f}, m2[5] = {0.f, 0.f, 0.f, 0.f, 0.f};
        float s;

        {   // S1: floats 0..31 -> p0..p4
            float A[32];
            #pragma unroll
            for (int i = 0; i < 8; ++i)
                *reinterpret_cast<float4*>(&A[4 * i]) = M4[i];
            m0 = fmaf(wv[0], x0r * A[0], m0);
            #pragma unroll
            for (int c = 0; c < 3; ++c) m1[c] = fmaf(wv[1], x0r * A[4 + c], m1[c]);
            #pragma unroll
            for (int c = 0; c < 5; ++c) m2[c] = fmaf(wv[2], x0r * A[8 + c], m2[c]);
            #pragma unroll
            for (int c = 0; c < 3; ++c) {
                s = x1r[0] * A[16 + c] + x1r[1] * A[19 + c] + x1r[2] * A[22 + c];
                m1[c] = fmaf(wv[3], s, m1[c]);
            }
            s = x1r[0] * A[28] + x1r[1] * A[29] + x1r[2] * A[30];
            m0 = fmaf(wv[4], s, m0);
        }
        {   // S2: floats 32..59 -> p5, p6
            float A[28];
            #pragma unroll
            for (int i = 0; i < 7; ++i)
                *reinterpret_cast<float4*>(&A[4 * i]) = M4[8 + i];
            #pragma unroll
            for (int c = 0; c < 5; ++c) {
                s = x1r[0] * A[c] + x1r[1] * A[5 + c] + x1r[2] * A[10 + c];
                m2[c] = fmaf(wv[5], s, m2[c]);
            }
            #pragma unroll
            for (int c = 0; c < 3; ++c) {
                s = x1r[0] * A[16 + c] + x1r[1] * A[19 + c] + x1r[2] * A[22 + c];
                m1[c] = fmaf(wv[6], s, m1[c]);
            }
        }
        {   // S3: floats 60..87 -> p7 (2,0,2): A[a*5+c]
            float A[28];
            #pragma unroll
            for (int i = 0; i < 7; ++i)
                *reinterpret_cast<float4*>(&A[4 * i]) = M4[15 + i];
            #pragma unroll
            for (int c = 0; c < 5; ++c) {
                s = 0.f;
                #pragma unroll
                for (int a = 0; a < 5; ++a) s = fmaf(x2r[a], A[a * 5 + c], s);
                m2[c] = fmaf(wv[7], s, m2[c]);
            }
        }
        {   // S4: floats 88..111 -> p8 (A[a*3+c]), p9 (A[16+a])
            float A[24];
            #pragma unroll
            for (int i = 0; i < 6; ++i)
                *reinterpret_cast<float4*>(&A[4 * i]) = M4[22 + i];
            #pragma unroll
            for (int c = 0; c < 3; ++c) {
                s = 0.f;
                #pragma unroll
                for (int a = 0; a < 5; ++a) s = fmaf(x2r[a], A[a * 3 + c], s);
                m1[c] = fmaf(wv[8], s, m1[c]);
            }
            s = 0.f;
            #pragma unroll
            for (int a = 0; a < 5; ++a) s = fmaf(x2r[a], A[16 + a], s);
            m0 = fmaf(wv[9], s, m0);
        }
        {   // S5: floats 112..136 -> p10 (2,2,2): A[a*5+c]
            float A[28];
            #pragma unroll
            for (int i = 0; i < 7; ++i)
                *reinterpret_cast<float4*>(&A[4 * i]) = M4[28 + i];
            #pragma unroll
            for (int c = 0; c < 5; ++c) {
                s = 0.f;
                #pragma unroll
                for (int a = 0; a < 5; ++a) s = fmaf(x2r[a], A[a * 5 + c], s);
                m2[c] = fmaf(wv[10], s, m2[c]);
            }
        }

        // coalesced channel-major atomic scatter (9 x red.f32, no staging)
        float* ob = g_outT + (size_t)dn * FEAT;
        red1(&ob[u], m0);
        #pragma unroll
        for (int a = 0; a < 3; ++a) red1(&ob[32 + a * 32 + u], m1[a]);
        #pragma unroll
        for (int a = 0; a < 5; ++a) red1(&ob[128 + a * 32 + u], m2[a]);
    }
}

// ---------------------------------------------------------------------------
extern "C" void kernel_launch(void* const* d_in, const int* in_sizes, int n_in,
                              void* d_out, int out_size) {
    const float* nodes = (const float*)d_in[0];
    const float* pos   = (const float*)d_in[1];
    const int*   src   = (const int*)d_in[2];
    const int*   dst   = (const int*)d_in[3];
    const float* w1    = (const float*)d_in[4];
    const float* b1    = (const float*)d_in[5];
    const float* w2    = (const float*)d_in[6];
    const float* b2    = (const float*)d_in[7];
    float* out = (float*)d_out;

    setup_kernel<<<SETUP_BLOCKS, 128>>>(nodes);
    rtab_kernel<<<(RTAB_ROWS + 1) / 2, 256>>>(w1, b1, w2, b2);

    cudaFuncSetAttribute(conv_kernel,
                         cudaFuncAttributeMaxDynamicSharedMemorySize, SMEM_BYTES);
    int nblocks = (N_EDGES + EPB - 1) / EPB;
    conv_kernel<<<nblocks, BLK, SMEM_BYTES>>>(pos, src, dst);

    untranspose_kernel<<<1024, 256>>>(out);
}